// round 1
// baseline (speedup 1.0000x reference)
#include <cuda_runtime.h>
#include <cstdint>

// Problem constants (fixed shapes)
constexpr int N_TOK = 16384;   // T*B = 2048*8
constexpr int C     = 512;
constexpr int O     = 512;
constexpr int RD    = 64;
constexpr int NE    = 8;
constexpr int KDIM  = (NE + 1) * C;   // 4608 : 8 expert slices + bias slice

// Scratch (static device globals — no allocation)
__device__ float g_resp[N_TOK * NE];
__device__ float g_denom[N_TOK];

// ---------------------------------------------------------------------------
// Phase 1: GMM responsibilities. One warp per token.
// ---------------------------------------------------------------------------
__global__ __launch_bounds__(256) void resp_kernel(
    const float* __restrict__ x, const float* __restrict__ map_w,
    const float* __restrict__ map_b, const float* __restrict__ cent,
    const float* __restrict__ prior)
{
    __shared__ float s_centT[RD * NE];   // [j][e]
    __shared__ float s_cc[NE];
    __shared__ float s_lp[NE];
    __shared__ float s_mb[RD];

    const int tid = threadIdx.x;
    for (int i = tid; i < RD * NE; i += 256) {
        int e = i / RD, j = i % RD;
        s_centT[j * NE + e] = cent[i];
    }
    if (tid < NE) {
        float cc = 0.f;
        #pragma unroll
        for (int j = 0; j < RD; ++j) { float c = cent[tid * RD + j]; cc = fmaf(c, c, cc); }
        s_cc[tid] = cc;
        s_lp[tid] = logf(prior[tid]);
    }
    if (tid < RD) s_mb[tid] = map_b[tid];
    __syncthreads();

    const int warp = tid >> 5, lane = tid & 31;
    const int token = blockIdx.x * 8 + warp;

    const float4* xr = (const float4*)(x + (size_t)token * C);
    const float4 xv0 = xr[lane], xv1 = xr[32 + lane], xv2 = xr[64 + lane], xv3 = xr[96 + lane];
    const float4* mw = (const float4*)map_w;

    float kk = 0.f;
    float kc[NE];
    #pragma unroll
    for (int e = 0; e < NE; ++e) kc[e] = 0.f;

    #pragma unroll 2
    for (int j = 0; j < RD; ++j) {
        const float4* wr = mw + j * 128;
        float4 w0 = wr[lane], w1 = wr[32 + lane], w2 = wr[64 + lane], w3 = wr[96 + lane];
        float p;
        p = xv0.x * w0.x;              p = fmaf(xv0.y, w0.y, p);
        p = fmaf(xv0.z, w0.z, p);      p = fmaf(xv0.w, w0.w, p);
        p = fmaf(xv1.x, w1.x, p);      p = fmaf(xv1.y, w1.y, p);
        p = fmaf(xv1.z, w1.z, p);      p = fmaf(xv1.w, w1.w, p);
        p = fmaf(xv2.x, w2.x, p);      p = fmaf(xv2.y, w2.y, p);
        p = fmaf(xv2.z, w2.z, p);      p = fmaf(xv2.w, w2.w, p);
        p = fmaf(xv3.x, w3.x, p);      p = fmaf(xv3.y, w3.y, p);
        p = fmaf(xv3.z, w3.z, p);      p = fmaf(xv3.w, w3.w, p);
        p += __shfl_xor_sync(0xffffffffu, p, 16);
        p += __shfl_xor_sync(0xffffffffu, p, 8);
        p += __shfl_xor_sync(0xffffffffu, p, 4);
        p += __shfl_xor_sync(0xffffffffu, p, 2);
        p += __shfl_xor_sync(0xffffffffu, p, 1);
        float kj = p + s_mb[j];
        kk = fmaf(kj, kj, kk);
        const float4 c01 = *(const float4*)&s_centT[j * NE + 0];
        const float4 c23 = *(const float4*)&s_centT[j * NE + 4];
        kc[0] = fmaf(kj, c01.x, kc[0]);  kc[1] = fmaf(kj, c01.y, kc[1]);
        kc[2] = fmaf(kj, c01.z, kc[2]);  kc[3] = fmaf(kj, c01.w, kc[3]);
        kc[4] = fmaf(kj, c23.x, kc[4]);  kc[5] = fmaf(kj, c23.y, kc[5]);
        kc[6] = fmaf(kj, c23.z, kc[6]);  kc[7] = fmaf(kj, c23.w, kc[7]);
    }

    // logresp, stable logsumexp (all lanes redundantly; lane 0 stores)
    const float LOG2PI = 1.8378770664093453f;
    float lr[NE], m = -1e30f;
    #pragma unroll
    for (int e = 0; e < NE; ++e) {
        lr[e] = -0.5f * (kk + s_cc[e] - 2.f * kc[e]) - (RD * 0.5f) * LOG2PI + s_lp[e];
        m = fmaxf(m, lr[e]);
    }
    float s = 0.f;
    #pragma unroll
    for (int e = 0; e < NE; ++e) s += expf(lr[e] - m);
    float denom = m + logf(s);
    if (lane == 0) {
        float4 r0, r1;
        r0.x = expf(lr[0] - denom); r0.y = expf(lr[1] - denom);
        r0.z = expf(lr[2] - denom); r0.w = expf(lr[3] - denom);
        r1.x = expf(lr[4] - denom); r1.y = expf(lr[5] - denom);
        r1.z = expf(lr[6] - denom); r1.w = expf(lr[7] - denom);
        *(float4*)&g_resp[token * NE + 0] = r0;
        *(float4*)&g_resp[token * NE + 4] = r1;
        g_denom[token] = denom;
    }
}

// ---------------------------------------------------------------------------
// Phase 2: fused big GEMM, TF32 mma.sync.  y = A_big @ B_big^T + bias_b
// A_big[n, e*512+i] = resp[n,e]*x[n,i] (e<8) ; x[n,i] (e==8)
// B_big[o, e*512+i] = pw_w[e, o*512+i] (e<8) ; bias_w[o,i] (e==8)
// ---------------------------------------------------------------------------
constexpr int BM = 128, BN = 128, BK = 32;

__device__ __forceinline__ unsigned f2tf32(float f) {
    unsigned u;
    asm("cvt.rna.tf32.f32 %0, %1;" : "=r"(u) : "f"(f));
    return u;
}

__device__ __forceinline__ void mma_tf32(float (&c)[4], const unsigned (&a)[4], const unsigned (&b)[2]) {
    asm volatile(
        "mma.sync.aligned.m16n8k8.row.col.f32.tf32.tf32.f32 "
        "{%0,%1,%2,%3}, {%4,%5,%6,%7}, {%8,%9}, {%0,%1,%2,%3};\n"
        : "+f"(c[0]), "+f"(c[1]), "+f"(c[2]), "+f"(c[3])
        : "r"(a[0]), "r"(a[1]), "r"(a[2]), "r"(a[3]), "r"(b[0]), "r"(b[1]));
}

__global__ __launch_bounds__(256, 2) void moe_gemm(
    const float* __restrict__ x, const float* __restrict__ pw_w,
    const float* __restrict__ bias_w, const float* __restrict__ bias_b,
    float* __restrict__ out)
{
    __shared__ float As[BM][BK + 4];  // [m][k], tf32 bit patterns
    __shared__ float Bs[BN][BK + 4];  // [n][k], tf32 bit patterns

    const int bm = blockIdx.x, bn = blockIdx.y;
    const int tid = threadIdx.x;
    const int warp = tid >> 5, lane = tid & 31;
    const int wm = warp & 3, wn = warp >> 2;   // warp grid 4 (M) x 2 (N); warp tile 32x64
    const int g = lane >> 2, tg = lane & 3;

    float acc[2][8][4];
    #pragma unroll
    for (int a = 0; a < 2; ++a)
        #pragma unroll
        for (int b = 0; b < 8; ++b)
            #pragma unroll
            for (int c = 0; c < 4; ++c) acc[a][b][c] = 0.f;

    const int af = (tid & 7) * 4;   // k offset within tile (float4 granularity)
    const int t8 = tid >> 3;        // 0..31

    for (int kt = 0; kt < KDIM / BK; ++kt) {
        const int kbase = kt * BK;
        const int e = kbase >> 9;         // slice id, constant across tile
        const int i0 = kbase & 511;       // offset within slice

        // ---- A tile: 128x32, resp-scaled x ----
        #pragma unroll
        for (int p = 0; p < 4; ++p) {
            const int m = t8 + 32 * p;
            const int row = bm * BM + m;
            const float s = (e < NE) ? g_resp[row * NE + e] : 1.0f;
            const float4 v = *(const float4*)(x + (size_t)row * C + i0 + af);
            float4 w;
            w.x = __uint_as_float(f2tf32(v.x * s));
            w.y = __uint_as_float(f2tf32(v.y * s));
            w.z = __uint_as_float(f2tf32(v.z * s));
            w.w = __uint_as_float(f2tf32(v.w * s));
            *(float4*)&As[m][af] = w;
        }
        // ---- B tile: 128(o) x 32(k) ----
        #pragma unroll
        for (int p = 0; p < 4; ++p) {
            const int n = bn * BN + t8 + 32 * p;   // o index
            const float* src = (e < NE)
                ? (pw_w + (size_t)e * O * C + (size_t)n * C + i0 + af)
                : (bias_w + (size_t)n * C + i0 + af);
            const float4 v = *(const float4*)src;
            float4 w;
            w.x = __uint_as_float(f2tf32(v.x));
            w.y = __uint_as_float(f2tf32(v.y));
            w.z = __uint_as_float(f2tf32(v.z));
            w.w = __uint_as_float(f2tf32(v.w));
            *(float4*)&Bs[t8 + 32 * p][af] = w;
        }
        __syncthreads();

        #pragma unroll
        for (int ks = 0; ks < 4; ++ks) {
            const int k0 = ks * 8;
            unsigned a[2][4], b[8][2];
            #pragma unroll
            for (int mt = 0; mt < 2; ++mt) {
                const int m = wm * 32 + mt * 16;
                a[mt][0] = __float_as_uint(As[m + g][k0 + tg]);
                a[mt][1] = __float_as_uint(As[m + g + 8][k0 + tg]);
                a[mt][2] = __float_as_uint(As[m + g][k0 + tg + 4]);
                a[mt][3] = __float_as_uint(As[m + g + 8][k0 + tg + 4]);
            }
            #pragma unroll
            for (int nt = 0; nt < 8; ++nt) {
                const int n = wn * 64 + nt * 8 + g;
                b[nt][0] = __float_as_uint(Bs[n][k0 + tg]);
                b[nt][1] = __float_as_uint(Bs[n][k0 + tg + 4]);
            }
            #pragma unroll
            for (int mt = 0; mt < 2; ++mt)
                #pragma unroll
                for (int nt = 0; nt < 8; ++nt)
                    mma_tf32(acc[mt][nt], a[mt], b[nt]);
        }
        __syncthreads();
    }

    // ---- epilogue: + bias_b, store ----
    #pragma unroll
    for (int mt = 0; mt < 2; ++mt) {
        const int r0 = bm * BM + wm * 32 + mt * 16 + g;
        #pragma unroll
        for (int nt = 0; nt < 8; ++nt) {
            const int col = bn * BN + wn * 64 + nt * 8 + tg * 2;
            const float b0 = __ldg(bias_b + col), b1 = __ldg(bias_b + col + 1);
            float2 v0 = make_float2(acc[mt][nt][0] + b0, acc[mt][nt][1] + b1);
            float2 v1 = make_float2(acc[mt][nt][2] + b0, acc[mt][nt][3] + b1);
            *(float2*)(out + (size_t)r0 * O + col)       = v0;
            *(float2*)(out + (size_t)(r0 + 8) * O + col) = v1;
        }
    }
}

// ---------------------------------------------------------------------------
// Phase 3: loss = -COMMIT * sum(denom), deterministic tree reduce
// ---------------------------------------------------------------------------
__global__ __launch_bounds__(256) void loss_kernel(float* __restrict__ out, int out_size)
{
    __shared__ float s[256];
    const int tid = threadIdx.x;
    float a = 0.f;
    for (int i = tid; i < N_TOK; i += 256) a += g_denom[i];
    s[tid] = a;
    __syncthreads();
    for (int w = 128; w > 0; w >>= 1) {
        if (tid < w) s[tid] += s[tid + w];
        __syncthreads();
    }
    if (tid == 0) {
        const float loss = -0.1f * s[0];
        for (long i = (long)N_TOK * O; i < out_size; ++i) out[i] = loss;
    }
}

// ---------------------------------------------------------------------------
extern "C" void kernel_launch(void* const* d_in, const int* in_sizes, int n_in,
                              void* d_out, int out_size)
{
    const float* x      = (const float*)d_in[0];
    // d_in[1] = key_feat, ignored by the forward pass
    const float* map_w  = (const float*)d_in[2];
    const float* map_b  = (const float*)d_in[3];
    const float* cent   = (const float*)d_in[4];
    const float* prior  = (const float*)d_in[5];
    const float* pw_w   = (const float*)d_in[6];
    const float* bias_w = (const float*)d_in[7];
    const float* bias_b = (const float*)d_in[8];
    float* out = (float*)d_out;

    resp_kernel<<<N_TOK / 8, 256>>>(x, map_w, map_b, cent, prior);

    dim3 grid(N_TOK / BM, O / BN);
    moe_gemm<<<grid, 256>>>(x, pw_w, bias_w, bias_b, out);

    loss_kernel<<<1, 256>>>(out, out_size);
}

// round 5
// speedup vs baseline: 1.9358x; 1.9358x over previous
#include <cuda_runtime.h>
#include <cuda_fp16.h>
#include <cstdint>

// ---------------------------------------------------------------------------
// Problem constants
// ---------------------------------------------------------------------------
constexpr int N_TOK = 16384;   // T*B
constexpr int C     = 512;
constexpr int O     = 512;
constexpr int RD    = 64;
constexpr int NE    = 8;
constexpr int NSL   = NE + 1;          // 8 expert slices + bias slice
constexpr int BM = 128, BN = 256, BK = 32;
constexpr int NKT = NSL * (C / BK);    // 144, ordered (i0, e): kt = i0*9 + e

// Scratch (static device globals — no allocation)
__device__ float g_resp[N_TOK * NE];
__device__ float g_denom[N_TOK];
__device__ __align__(16) __half g_wh[NSL * O * C];   // fp16 weights: experts 0..7, then bias_w

// ---------------------------------------------------------------------------
// Helpers
// ---------------------------------------------------------------------------
__device__ __forceinline__ uint32_t smem_u32(const void* p) {
    uint32_t a;
    asm("{ .reg .u64 t; cvta.to.shared.u64 t, %1; cvt.u32.u64 %0, t; }" : "=r"(a) : "l"(p));
    return a;
}
__device__ __forceinline__ void cpa16(uint32_t dst, const void* src) {
    asm volatile("cp.async.cg.shared.global [%0], [%1], 16;" :: "r"(dst), "l"(src));
}
#define CP_COMMIT() asm volatile("cp.async.commit_group;" ::: "memory")
#define CP_WAIT0()  asm volatile("cp.async.wait_group 0;" ::: "memory")

__device__ __forceinline__ uint32_t pack_h2(float lo, float hi) {
    __half2 h = __floats2half2_rn(lo, hi);     // .x = lo (low 16 bits)
    return *reinterpret_cast<uint32_t*>(&h);
}
__device__ __forceinline__ void mma_f16(float (&c)[4], const uint32_t (&a)[4], const uint32_t (&b)[2]) {
    asm volatile(
        "mma.sync.aligned.m16n8k16.row.col.f32.f16.f16.f32 "
        "{%0,%1,%2,%3}, {%4,%5,%6,%7}, {%8,%9}, {%0,%1,%2,%3};\n"
        : "+f"(c[0]), "+f"(c[1]), "+f"(c[2]), "+f"(c[3])
        : "r"(a[0]), "r"(a[1]), "r"(a[2]), "r"(a[3]), "r"(b[0]), "r"(b[1]));
}

// ---------------------------------------------------------------------------
// Phase 0: convert weights to fp16.  g_wh[(e*O + o)*C + c]; slice 8 = bias_w.
// ---------------------------------------------------------------------------
__global__ __launch_bounds__(256) void prep_kernel(const float* __restrict__ pw,
                                                   const float* __restrict__ bw)
{
    const int stride = gridDim.x * blockDim.x;
    const int nTot = NSL * O * C / 4;        // float4 count
    const int nPw  = NE  * O * C / 4;
    for (int f = blockIdx.x * blockDim.x + threadIdx.x; f < nTot; f += stride) {
        float4 v = (f < nPw) ? ((const float4*)pw)[f] : ((const float4*)bw)[f - nPw];
        uint2 h;
        h.x = pack_h2(v.x, v.y);
        h.y = pack_h2(v.z, v.w);
        ((uint2*)g_wh)[f] = h;
    }
}

// ---------------------------------------------------------------------------
// Phase 1: GMM responsibilities. Block = 64 tokens, register-tiled projection.
// ---------------------------------------------------------------------------
__global__ __launch_bounds__(256) void resp_kernel(
    const float* __restrict__ x, const float* __restrict__ map_w,
    const float* __restrict__ map_b, const float* __restrict__ cent,
    const float* __restrict__ prior)
{
    __shared__ float xs[16][68];     // [k][token]
    __shared__ float ws[16][68];     // [k][rd]
    __shared__ float s_k[64][65];    // [token][rd]
    __shared__ float s_cent[NE][RD];
    __shared__ float s_cc[NE], s_lp[NE], s_mb[RD];

    const int tid = threadIdx.x;
    const int t0 = blockIdx.x * 64;

    for (int i = tid; i < NE * RD; i += 256) s_cent[i / RD][i % RD] = cent[i];
    if (tid < NE) {
        float cc = 0.f;
        #pragma unroll
        for (int j = 0; j < RD; ++j) { float c = cent[tid * RD + j]; cc = fmaf(c, c, cc); }
        s_cc[tid] = cc;
        s_lp[tid] = logf(prior[tid]);
    }
    if (tid < RD) s_mb[tid] = map_b[tid];

    const int ty = tid >> 4, tx = tid & 15;
    const int lr = tid >> 2, lq = tid & 3;

    float acc[4][4];
    #pragma unroll
    for (int i = 0; i < 4; ++i)
        #pragma unroll
        for (int j = 0; j < 4; ++j) acc[i][j] = 0.f;

    for (int ct = 0; ct < C / 16; ++ct) {
        const float4 xv = *(const float4*)(x     + (size_t)(t0 + lr) * C + ct * 16 + lq * 4);
        const float4 wv = *(const float4*)(map_w + (size_t)lr        * C + ct * 16 + lq * 4);
        __syncthreads();
        xs[lq * 4 + 0][lr] = xv.x; xs[lq * 4 + 1][lr] = xv.y;
        xs[lq * 4 + 2][lr] = xv.z; xs[lq * 4 + 3][lr] = xv.w;
        ws[lq * 4 + 0][lr] = wv.x; ws[lq * 4 + 1][lr] = wv.y;
        ws[lq * 4 + 2][lr] = wv.z; ws[lq * 4 + 3][lr] = wv.w;
        __syncthreads();
        #pragma unroll
        for (int kk = 0; kk < 16; ++kk) {
            const float4 a = *(const float4*)&xs[kk][ty * 4];
            const float4 b = *(const float4*)&ws[kk][tx * 4];
            const float av[4] = {a.x, a.y, a.z, a.w};
            const float bv[4] = {b.x, b.y, b.z, b.w};
            #pragma unroll
            for (int i = 0; i < 4; ++i)
                #pragma unroll
                for (int j = 0; j < 4; ++j) acc[i][j] = fmaf(av[i], bv[j], acc[i][j]);
        }
    }
    __syncthreads();
    #pragma unroll
    for (int i = 0; i < 4; ++i)
        #pragma unroll
        for (int j = 0; j < 4; ++j)
            s_k[ty * 4 + i][tx * 4 + j] = acc[i][j] + s_mb[tx * 4 + j];
    __syncthreads();

    if (tid < 64) {
        float kk = 0.f, kc[NE];
        #pragma unroll
        for (int e = 0; e < NE; ++e) kc[e] = 0.f;
        #pragma unroll 8
        for (int j = 0; j < RD; ++j) {
            const float kj = s_k[tid][j];
            kk = fmaf(kj, kj, kk);
            #pragma unroll
            for (int e = 0; e < NE; ++e) kc[e] = fmaf(kj, s_cent[e][j], kc[e]);
        }
        const float LOG2PI = 1.8378770664093453f;
        float lr8[NE], m = -1e30f;
        #pragma unroll
        for (int e = 0; e < NE; ++e) {
            lr8[e] = -0.5f * (kk + s_cc[e] - 2.f * kc[e]) - (RD * 0.5f) * LOG2PI + s_lp[e];
            m = fmaxf(m, lr8[e]);
        }
        float s = 0.f;
        #pragma unroll
        for (int e = 0; e < NE; ++e) s += expf(lr8[e] - m);
        const float denom = m + logf(s);
        float4 r0, r1;
        r0.x = expf(lr8[0] - denom); r0.y = expf(lr8[1] - denom);
        r0.z = expf(lr8[2] - denom); r0.w = expf(lr8[3] - denom);
        r1.x = expf(lr8[4] - denom); r1.y = expf(lr8[5] - denom);
        r1.z = expf(lr8[6] - denom); r1.w = expf(lr8[7] - denom);
        const int tok = t0 + tid;
        *(float4*)&g_resp[tok * NE + 0] = r0;
        *(float4*)&g_resp[tok * NE + 4] = r1;
        g_denom[tok] = denom;
    }
}

// ---------------------------------------------------------------------------
// Phase 2: fp16 mma.sync GEMM.  y = A_big @ B_big^T + bias_b
//   A_big[n, (i0,e)] = resp[n,e]*x[n,i] (e<8) ; x[n,i] (e==8)
//   K ordered (i0-chunk, e): x chunk stays in registers across the 9 slices.
//   BM=128, BN=256, BK=32; 8 warps, warp tile 64x64; double-buffered cp.async B.
// ---------------------------------------------------------------------------
// SMEM layout (bytes). A rows padded to 40 halves (80B, 16B-aligned, bank-clean).
constexpr uint32_t OFF_RESP = 0;       // 128*8*4      = 4096
constexpr uint32_t OFF_BIAS = 4096;    // 256*4        = 1024
constexpr uint32_t OFF_A0   = 5120;    // 128*80       = 10240
constexpr uint32_t OFF_A1   = 15360;
constexpr uint32_t OFF_B0   = 25600;   // 256*80       = 20480
constexpr uint32_t OFF_B1   = 46080;
constexpr uint32_t SMEM_TOTAL = 66560;

__global__ __launch_bounds__(256, 1) void moe_gemm(
    const float* __restrict__ x, const float* __restrict__ bias_b,
    float* __restrict__ out)
{
    extern __shared__ __align__(128) char smem[];
    const uint32_t sb = smem_u32(smem);

    const int tid = threadIdx.x;
    const int warp = tid >> 5, lane = tid & 31;
    const int wm = warp >> 2, wn = warp & 3;       // 2 (M) x 4 (N); warp tile 64x64
    const int g = lane >> 2, tg = lane & 3;
    const int bm = blockIdx.x, bn = blockIdx.y;

    const int arow = tid >> 1;          // 0..127 : A row this thread builds
    const int aseg = tid & 1;           // 16-half segment within row

    float* respS = (float*)(smem + OFF_RESP);
    float* biasS = (float*)(smem + OFF_BIAS);

    // preload resp tile + bias_b slice
    ((float4*)respS)[tid] = ((const float4*)(g_resp + (size_t)bm * BM * NE))[tid];
    if (tid < 64) ((float4*)biasS)[tid] = ((const float4*)(bias_b + bn * BN))[tid];

    float4 xv[4];   // 16 x-values for current i0 chunk
    auto ldgX = [&](int i0c) {
        const float4* p = (const float4*)(x + (size_t)(bm * BM + arow) * C + i0c + aseg * 16);
        xv[0] = p[0]; xv[1] = p[1]; xv[2] = p[2]; xv[3] = p[3];
    };
    auto stsA = [&](int e, uint32_t offA) {
        const float s = (e < NE) ? respS[arow * NE + e] : 1.0f;
        uint4 h0, h1;
        h0.x = pack_h2(xv[0].x * s, xv[0].y * s);
        h0.y = pack_h2(xv[0].z * s, xv[0].w * s);
        h0.z = pack_h2(xv[1].x * s, xv[1].y * s);
        h0.w = pack_h2(xv[1].z * s, xv[1].w * s);
        h1.x = pack_h2(xv[2].x * s, xv[2].y * s);
        h1.y = pack_h2(xv[2].z * s, xv[2].w * s);
        h1.z = pack_h2(xv[3].x * s, xv[3].y * s);
        h1.w = pack_h2(xv[3].z * s, xv[3].w * s);
        uint4* dst = (uint4*)(smem + offA + arow * 80 + aseg * 32);
        dst[0] = h0; dst[1] = h1;
    };
    auto issueB = [&](int e, int i0c, uint32_t offB) {
        const __half* base = g_wh + ((size_t)e * O + bn * BN) * C + i0c;
        #pragma unroll
        for (int k = 0; k < 4; ++k) {
            const int c = tid + k * 256;
            const int row = c >> 2, q = c & 3;
            cpa16(sb + offB + row * 80 + q * 16, base + (size_t)row * C + q * 8);
        }
    };

    float acc[4][8][4];
    #pragma unroll
    for (int a = 0; a < 4; ++a)
        #pragma unroll
        for (int b = 0; b < 8; ++b)
            #pragma unroll
            for (int c = 0; c < 4; ++c) acc[a][b][c] = 0.f;

    // prologue: stage 0
    ldgX(0);
    issueB(0, 0, OFF_B0);
    CP_COMMIT();
    __syncthreads();           // resp/bias visible
    stsA(0, OFF_A0);
    CP_WAIT0();
    __syncthreads();

    for (int kt = 0; kt < NKT; ++kt) {
        const int s = kt & 1;
        const bool more = (kt + 1 < NKT);
        int e1 = 0, i1 = 0;
        if (more) {
            e1 = (kt + 1) % NSL;
            i1 = ((kt + 1) / NSL) * BK;
            issueB(e1, i1, s ? OFF_B0 : OFF_B1);
            CP_COMMIT();
            if (e1 == 0) ldgX(i1);        // new x chunk, hidden under compute
        }

        // compute on stage s
        {
            const uint32_t* As32 = (const uint32_t*)(smem + (s ? OFF_A1 : OFF_A0));
            const uint32_t* Bs32 = (const uint32_t*)(smem + (s ? OFF_B1 : OFF_B0));
            #pragma unroll
            for (int ks = 0; ks < 2; ++ks) {
                const int kb = ks * 8;
                uint32_t a[4][2 * 2], b[8][2];
                #pragma unroll
                for (int mt = 0; mt < 4; ++mt) {
                    const int m = wm * 64 + mt * 16;
                    a[mt][0] = As32[(m + g) * 20 + kb + tg];
                    a[mt][1] = As32[(m + g + 8) * 20 + kb + tg];
                    a[mt][2] = As32[(m + g) * 20 + kb + tg + 4];
                    a[mt][3] = As32[(m + g + 8) * 20 + kb + tg + 4];
                }
                #pragma unroll
                for (int nt = 0; nt < 8; ++nt) {
                    const int n = wn * 64 + nt * 8 + g;
                    b[nt][0] = Bs32[n * 20 + kb + tg];
                    b[nt][1] = Bs32[n * 20 + kb + tg + 4];
                }
                #pragma unroll
                for (int mt = 0; mt < 4; ++mt)
                    #pragma unroll
                    for (int nt = 0; nt < 8; ++nt)
                        mma_f16(acc[mt][nt], a[mt], b[nt]);
            }
        }

        if (more) {
            stsA(e1, s ? OFF_A0 : OFF_A1);
            CP_WAIT0();
        }
        __syncthreads();
    }

    // epilogue: + bias_b, store float2 pairs
    #pragma unroll
    for (int mt = 0; mt < 4; ++mt) {
        const int row = bm * BM + wm * 64 + mt * 16 + g;
        #pragma unroll
        for (int nt = 0; nt < 8; ++nt) {
            const int cb = wn * 64 + nt * 8 + tg * 2;
            const float b0 = biasS[cb], b1 = biasS[cb + 1];
            float2 v0 = make_float2(acc[mt][nt][0] + b0, acc[mt][nt][1] + b1);
            float2 v1 = make_float2(acc[mt][nt][2] + b0, acc[mt][nt][3] + b1);
            float* dst = out + (size_t)row * O + bn * BN + cb;
            *(float2*)dst = v0;
            *(float2*)(dst + 8 * O) = v1;
        }
    }
}

// ---------------------------------------------------------------------------
// Phase 3: loss = -COMMIT * sum(denom)
// ---------------------------------------------------------------------------
__global__ __launch_bounds__(256) void loss_kernel(float* __restrict__ out, int out_size)
{
    __shared__ float s[256];
    const int tid = threadIdx.x;
    float a = 0.f;
    for (int i = tid; i < N_TOK; i += 256) a += g_denom[i];
    s[tid] = a;
    __syncthreads();
    for (int w = 128; w > 0; w >>= 1) {
        if (tid < w) s[tid] += s[tid + w];
        __syncthreads();
    }
    if (tid == 0) {
        const float loss = -0.1f * s[0];
        for (long i = (long)N_TOK * O; i < out_size; ++i) out[i] = loss;
    }
}

// ---------------------------------------------------------------------------
extern "C" void kernel_launch(void* const* d_in, const int* in_sizes, int n_in,
                              void* d_out, int out_size)
{
    const float* x      = (const float*)d_in[0];
    // d_in[1] = key_feat, ignored by the forward pass
    const float* map_w  = (const float*)d_in[2];
    const float* map_b  = (const float*)d_in[3];
    const float* cent   = (const float*)d_in[4];
    const float* prior  = (const float*)d_in[5];
    const float* pw_w   = (const float*)d_in[6];
    const float* bias_w = (const float*)d_in[7];
    const float* bias_b = (const float*)d_in[8];
    float* out = (float*)d_out;

    cudaFuncSetAttribute(moe_gemm, cudaFuncAttributeMaxDynamicSharedMemorySize, SMEM_TOTAL);

    prep_kernel<<<576, 256>>>(pw_w, bias_w);
    resp_kernel<<<N_TOK / 64, 256>>>(x, map_w, map_b, cent, prior);
    dim3 grid(N_TOK / BM, O / BN);
    moe_gemm<<<grid, 256, SMEM_TOTAL>>>(x, bias_b, out);
    loss_kernel<<<1, 256>>>(out, out_size);
}

// round 6
// speedup vs baseline: 1.9416x; 1.0030x over previous
#include <cuda_runtime.h>
#include <cuda_fp16.h>
#include <cstdint>

// ---------------------------------------------------------------------------
// Problem constants
// ---------------------------------------------------------------------------
constexpr int N_TOK = 16384;   // T*B
constexpr int C     = 512;
constexpr int O     = 512;
constexpr int RD    = 64;
constexpr int NE    = 8;
constexpr int NSL   = NE + 1;          // 8 expert slices + bias slice
constexpr int BM = 128, BN = 256, BK = 32;
constexpr int NKT = NSL * (C / BK);    // 144, ordered (i0, e): kt = i0*9 + e

// Scratch (static device globals — no allocation)
__device__ float g_resp[N_TOK * NE];
__device__ float g_denom[N_TOK];
__device__ __align__(16) __half g_wh[NSL * O * C];   // fp16 weights: experts 0..7, then bias_w

// ---------------------------------------------------------------------------
// Helpers
// ---------------------------------------------------------------------------
__device__ __forceinline__ uint32_t smem_u32(const void* p) {
    uint32_t a;
    asm("{ .reg .u64 t; cvta.to.shared.u64 t, %1; cvt.u32.u64 %0, t; }" : "=r"(a) : "l"(p));
    return a;
}
__device__ __forceinline__ void cpa16(uint32_t dst, const void* src) {
    asm volatile("cp.async.cg.shared.global [%0], [%1], 16;" :: "r"(dst), "l"(src));
}
#define CP_COMMIT() asm volatile("cp.async.commit_group;" ::: "memory")
#define CP_WAIT0()  asm volatile("cp.async.wait_group 0;" ::: "memory")

__device__ __forceinline__ uint32_t pack_h2(float lo, float hi) {
    __half2 h = __floats2half2_rn(lo, hi);     // .x = lo (low 16 bits)
    return *reinterpret_cast<uint32_t*>(&h);
}
__device__ __forceinline__ void mma_f16(float (&c)[4], const uint32_t (&a)[4], const uint32_t (&b)[2]) {
    asm volatile(
        "mma.sync.aligned.m16n8k16.row.col.f32.f16.f16.f32 "
        "{%0,%1,%2,%3}, {%4,%5,%6,%7}, {%8,%9}, {%0,%1,%2,%3};\n"
        : "+f"(c[0]), "+f"(c[1]), "+f"(c[2]), "+f"(c[3])
        : "r"(a[0]), "r"(a[1]), "r"(a[2]), "r"(a[3]), "r"(b[0]), "r"(b[1]));
}

// ---------------------------------------------------------------------------
// Phase 0: convert weights to fp16.  g_wh[(e*O + o)*C + c]; slice 8 = bias_w.
// ---------------------------------------------------------------------------
__global__ __launch_bounds__(256) void prep_kernel(const float* __restrict__ pw,
                                                   const float* __restrict__ bw)
{
    const int stride = gridDim.x * blockDim.x;
    const int nTot = NSL * O * C / 4;        // float4 count
    const int nPw  = NE  * O * C / 4;
    for (int f = blockIdx.x * blockDim.x + threadIdx.x; f < nTot; f += stride) {
        float4 v = (f < nPw) ? ((const float4*)pw)[f] : ((const float4*)bw)[f - nPw];
        uint2 h;
        h.x = pack_h2(v.x, v.y);
        h.y = pack_h2(v.z, v.w);
        ((uint2*)g_wh)[f] = h;
    }
}

// ---------------------------------------------------------------------------
// Phase 1: GMM responsibilities. Block = 64 tokens, register-tiled projection.
// ---------------------------------------------------------------------------
__global__ __launch_bounds__(256) void resp_kernel(
    const float* __restrict__ x, const float* __restrict__ map_w,
    const float* __restrict__ map_b, const float* __restrict__ cent,
    const float* __restrict__ prior)
{
    __shared__ float xs[16][68];     // [k][token]
    __shared__ float ws[16][68];     // [k][rd]
    __shared__ float s_k[64][65];    // [token][rd]
    __shared__ float s_cent[NE][RD];
    __shared__ float s_cc[NE], s_lp[NE], s_mb[RD];

    const int tid = threadIdx.x;
    const int t0 = blockIdx.x * 64;

    for (int i = tid; i < NE * RD; i += 256) s_cent[i / RD][i % RD] = cent[i];
    if (tid < NE) {
        float cc = 0.f;
        #pragma unroll
        for (int j = 0; j < RD; ++j) { float c = cent[tid * RD + j]; cc = fmaf(c, c, cc); }
        s_cc[tid] = cc;
        s_lp[tid] = logf(prior[tid]);
    }
    if (tid < RD) s_mb[tid] = map_b[tid];

    const int ty = tid >> 4, tx = tid & 15;
    const int lr = tid >> 2, lq = tid & 3;

    float acc[4][4];
    #pragma unroll
    for (int i = 0; i < 4; ++i)
        #pragma unroll
        for (int j = 0; j < 4; ++j) acc[i][j] = 0.f;

    for (int ct = 0; ct < C / 16; ++ct) {
        const float4 xv = *(const float4*)(x     + (size_t)(t0 + lr) * C + ct * 16 + lq * 4);
        const float4 wv = *(const float4*)(map_w + (size_t)lr        * C + ct * 16 + lq * 4);
        __syncthreads();
        xs[lq * 4 + 0][lr] = xv.x; xs[lq * 4 + 1][lr] = xv.y;
        xs[lq * 4 + 2][lr] = xv.z; xs[lq * 4 + 3][lr] = xv.w;
        ws[lq * 4 + 0][lr] = wv.x; ws[lq * 4 + 1][lr] = wv.y;
        ws[lq * 4 + 2][lr] = wv.z; ws[lq * 4 + 3][lr] = wv.w;
        __syncthreads();
        #pragma unroll
        for (int kk = 0; kk < 16; ++kk) {
            const float4 a = *(const float4*)&xs[kk][ty * 4];
            const float4 b = *(const float4*)&ws[kk][tx * 4];
            const float av[4] = {a.x, a.y, a.z, a.w};
            const float bv[4] = {b.x, b.y, b.z, b.w};
            #pragma unroll
            for (int i = 0; i < 4; ++i)
                #pragma unroll
                for (int j = 0; j < 4; ++j) acc[i][j] = fmaf(av[i], bv[j], acc[i][j]);
        }
    }
    __syncthreads();
    #pragma unroll
    for (int i = 0; i < 4; ++i)
        #pragma unroll
        for (int j = 0; j < 4; ++j)
            s_k[ty * 4 + i][tx * 4 + j] = acc[i][j] + s_mb[tx * 4 + j];
    __syncthreads();

    if (tid < 64) {
        float kk = 0.f, kc[NE];
        #pragma unroll
        for (int e = 0; e < NE; ++e) kc[e] = 0.f;
        #pragma unroll 8
        for (int j = 0; j < RD; ++j) {
            const float kj = s_k[tid][j];
            kk = fmaf(kj, kj, kk);
            #pragma unroll
            for (int e = 0; e < NE; ++e) kc[e] = fmaf(kj, s_cent[e][j], kc[e]);
        }
        const float LOG2PI = 1.8378770664093453f;
        float lr8[NE], m = -1e30f;
        #pragma unroll
        for (int e = 0; e < NE; ++e) {
            lr8[e] = -0.5f * (kk + s_cc[e] - 2.f * kc[e]) - (RD * 0.5f) * LOG2PI + s_lp[e];
            m = fmaxf(m, lr8[e]);
        }
        float s = 0.f;
        #pragma unroll
        for (int e = 0; e < NE; ++e) s += expf(lr8[e] - m);
        const float denom = m + logf(s);
        float4 r0, r1;
        r0.x = expf(lr8[0] - denom); r0.y = expf(lr8[1] - denom);
        r0.z = expf(lr8[2] - denom); r0.w = expf(lr8[3] - denom);
        r1.x = expf(lr8[4] - denom); r1.y = expf(lr8[5] - denom);
        r1.z = expf(lr8[6] - denom); r1.w = expf(lr8[7] - denom);
        const int tok = t0 + tid;
        *(float4*)&g_resp[tok * NE + 0] = r0;
        *(float4*)&g_resp[tok * NE + 4] = r1;
        g_denom[tok] = denom;
    }
}

// ---------------------------------------------------------------------------
// Phase 2: fp16 mma.sync GEMM.  y = A_big @ B_big^T + bias_b
//   A_big[n, (i0,e)] = resp[n,e]*x[n,i] (e<8) ; x[n,i] (e==8)
//   K ordered (i0-chunk, e): x chunk stays in registers across the 9 slices.
//   BM=128, BN=256, BK=32; 8 warps, warp tile 64x64; double-buffered cp.async B.
// ---------------------------------------------------------------------------
// SMEM layout (bytes). A rows padded to 40 halves (80B, 16B-aligned, bank-clean).
constexpr uint32_t OFF_RESP = 0;       // 128*8*4      = 4096
constexpr uint32_t OFF_BIAS = 4096;    // 256*4        = 1024
constexpr uint32_t OFF_A0   = 5120;    // 128*80       = 10240
constexpr uint32_t OFF_A1   = 15360;
constexpr uint32_t OFF_B0   = 25600;   // 256*80       = 20480
constexpr uint32_t OFF_B1   = 46080;
constexpr uint32_t SMEM_TOTAL = 66560;

__global__ __launch_bounds__(256, 1) void moe_gemm(
    const float* __restrict__ x, const float* __restrict__ bias_b,
    float* __restrict__ out)
{
    extern __shared__ __align__(128) char smem[];
    const uint32_t sb = smem_u32(smem);

    const int tid = threadIdx.x;
    const int warp = tid >> 5, lane = tid & 31;
    const int wm = warp >> 2, wn = warp & 3;       // 2 (M) x 4 (N); warp tile 64x64
    const int g = lane >> 2, tg = lane & 3;
    const int bm = blockIdx.x, bn = blockIdx.y;

    const int arow = tid >> 1;          // 0..127 : A row this thread builds
    const int aseg = tid & 1;           // 16-half segment within row

    float* respS = (float*)(smem + OFF_RESP);
    float* biasS = (float*)(smem + OFF_BIAS);

    // preload resp tile + bias_b slice
    ((float4*)respS)[tid] = ((const float4*)(g_resp + (size_t)bm * BM * NE))[tid];
    if (tid < 64) ((float4*)biasS)[tid] = ((const float4*)(bias_b + bn * BN))[tid];

    float4 xv[4];   // 16 x-values for current i0 chunk
    auto ldgX = [&](int i0c) {
        const float4* p = (const float4*)(x + (size_t)(bm * BM + arow) * C + i0c + aseg * 16);
        xv[0] = p[0]; xv[1] = p[1]; xv[2] = p[2]; xv[3] = p[3];
    };
    auto stsA = [&](int e, uint32_t offA) {
        const float s = (e < NE) ? respS[arow * NE + e] : 1.0f;
        uint4 h0, h1;
        h0.x = pack_h2(xv[0].x * s, xv[0].y * s);
        h0.y = pack_h2(xv[0].z * s, xv[0].w * s);
        h0.z = pack_h2(xv[1].x * s, xv[1].y * s);
        h0.w = pack_h2(xv[1].z * s, xv[1].w * s);
        h1.x = pack_h2(xv[2].x * s, xv[2].y * s);
        h1.y = pack_h2(xv[2].z * s, xv[2].w * s);
        h1.z = pack_h2(xv[3].x * s, xv[3].y * s);
        h1.w = pack_h2(xv[3].z * s, xv[3].w * s);
        uint4* dst = (uint4*)(smem + offA + arow * 80 + aseg * 32);
        dst[0] = h0; dst[1] = h1;
    };
    auto issueB = [&](int e, int i0c, uint32_t offB) {
        const __half* base = g_wh + ((size_t)e * O + bn * BN) * C + i0c;
        #pragma unroll
        for (int k = 0; k < 4; ++k) {
            const int c = tid + k * 256;
            const int row = c >> 2, q = c & 3;
            cpa16(sb + offB + row * 80 + q * 16, base + (size_t)row * C + q * 8);
        }
    };

    float acc[4][8][4];
    #pragma unroll
    for (int a = 0; a < 4; ++a)
        #pragma unroll
        for (int b = 0; b < 8; ++b)
            #pragma unroll
            for (int c = 0; c < 4; ++c) acc[a][b][c] = 0.f;

    // prologue: stage 0
    ldgX(0);
    issueB(0, 0, OFF_B0);
    CP_COMMIT();
    __syncthreads();           // resp/bias visible
    stsA(0, OFF_A0);
    CP_WAIT0();
    __syncthreads();

    for (int kt = 0; kt < NKT; ++kt) {
        const int s = kt & 1;
        const bool more = (kt + 1 < NKT);
        int e1 = 0, i1 = 0;
        if (more) {
            e1 = (kt + 1) % NSL;
            i1 = ((kt + 1) / NSL) * BK;
            issueB(e1, i1, s ? OFF_B0 : OFF_B1);
            CP_COMMIT();
            if (e1 == 0) ldgX(i1);        // new x chunk, hidden under compute
        }

        // compute on stage s
        {
            const uint32_t* As32 = (const uint32_t*)(smem + (s ? OFF_A1 : OFF_A0));
            const uint32_t* Bs32 = (const uint32_t*)(smem + (s ? OFF_B1 : OFF_B0));
            #pragma unroll
            for (int ks = 0; ks < 2; ++ks) {
                const int kb = ks * 8;
                uint32_t a[4][2 * 2], b[8][2];
                #pragma unroll
                for (int mt = 0; mt < 4; ++mt) {
                    const int m = wm * 64 + mt * 16;
                    a[mt][0] = As32[(m + g) * 20 + kb + tg];
                    a[mt][1] = As32[(m + g + 8) * 20 + kb + tg];
                    a[mt][2] = As32[(m + g) * 20 + kb + tg + 4];
                    a[mt][3] = As32[(m + g + 8) * 20 + kb + tg + 4];
                }
                #pragma unroll
                for (int nt = 0; nt < 8; ++nt) {
                    const int n = wn * 64 + nt * 8 + g;
                    b[nt][0] = Bs32[n * 20 + kb + tg];
                    b[nt][1] = Bs32[n * 20 + kb + tg + 4];
                }
                #pragma unroll
                for (int mt = 0; mt < 4; ++mt)
                    #pragma unroll
                    for (int nt = 0; nt < 8; ++nt)
                        mma_f16(acc[mt][nt], a[mt], b[nt]);
            }
        }

        if (more) {
            stsA(e1, s ? OFF_A0 : OFF_A1);
            CP_WAIT0();
        }
        __syncthreads();
    }

    // epilogue: + bias_b, store float2 pairs
    #pragma unroll
    for (int mt = 0; mt < 4; ++mt) {
        const int row = bm * BM + wm * 64 + mt * 16 + g;
        #pragma unroll
        for (int nt = 0; nt < 8; ++nt) {
            const int cb = wn * 64 + nt * 8 + tg * 2;
            const float b0 = biasS[cb], b1 = biasS[cb + 1];
            float2 v0 = make_float2(acc[mt][nt][0] + b0, acc[mt][nt][1] + b1);
            float2 v1 = make_float2(acc[mt][nt][2] + b0, acc[mt][nt][3] + b1);
            float* dst = out + (size_t)row * O + bn * BN + cb;
            *(float2*)dst = v0;
            *(float2*)(dst + 8 * O) = v1;
        }
    }
}

// ---------------------------------------------------------------------------
// Phase 3: loss = -COMMIT * sum(denom)
// ---------------------------------------------------------------------------
__global__ __launch_bounds__(256) void loss_kernel(float* __restrict__ out, int out_size)
{
    __shared__ float s[256];
    const int tid = threadIdx.x;
    float a = 0.f;
    for (int i = tid; i < N_TOK; i += 256) a += g_denom[i];
    s[tid] = a;
    __syncthreads();
    for (int w = 128; w > 0; w >>= 1) {
        if (tid < w) s[tid] += s[tid + w];
        __syncthreads();
    }
    if (tid == 0) {
        const float loss = -0.1f * s[0];
        for (long i = (long)N_TOK * O; i < out_size; ++i) out[i] = loss;
    }
}

// ---------------------------------------------------------------------------
extern "C" void kernel_launch(void* const* d_in, const int* in_sizes, int n_in,
                              void* d_out, int out_size)
{
    const float* x      = (const float*)d_in[0];
    // d_in[1] = key_feat, ignored by the forward pass
    const float* map_w  = (const float*)d_in[2];
    const float* map_b  = (const float*)d_in[3];
    const float* cent   = (const float*)d_in[4];
    const float* prior  = (const float*)d_in[5];
    const float* pw_w   = (const float*)d_in[6];
    const float* bias_w = (const float*)d_in[7];
    const float* bias_b = (const float*)d_in[8];
    float* out = (float*)d_out;

    cudaFuncSetAttribute(moe_gemm, cudaFuncAttributeMaxDynamicSharedMemorySize, SMEM_TOTAL);

    prep_kernel<<<576, 256>>>(pw_w, bias_w);
    resp_kernel<<<N_TOK / 64, 256>>>(x, map_w, map_b, cent, prior);
    dim3 grid(N_TOK / BM, O / BN);
    moe_gemm<<<grid, 256, SMEM_TOTAL>>>(x, bias_b, out);
    loss_kernel<<<1, 256>>>(out, out_size);
}

// round 8
// speedup vs baseline: 2.0331x; 1.0471x over previous
#include <cuda_runtime.h>
#include <cuda_fp16.h>
#include <cstdint>

// ---------------------------------------------------------------------------
// Problem constants
// ---------------------------------------------------------------------------
constexpr int N_TOK = 16384;   // T*B
constexpr int C     = 512;
constexpr int O     = 512;
constexpr int RD    = 64;
constexpr int NE    = 8;
constexpr int NSL   = NE + 1;          // 8 expert slices + bias slice
constexpr int BM = 128, BN = 256, BK = 32;
constexpr int NKT = NSL * (C / BK);    // 144, ordered (i0, e): kt = i0*9 + e
constexpr unsigned NTILES = (N_TOK / BM) * (O / BN);   // 256

// Scratch (static device globals — no allocation)
__device__ float g_resp[N_TOK * NE];
__device__ float g_psum[N_TOK / 64];                 // per-resp-block denom sums
__device__ __align__(16) __half g_wh[NSL * O * C];   // fp16 weights: experts 0..7, then bias_w
__device__ unsigned g_tile_ctr;

// ---------------------------------------------------------------------------
// Helpers
// ---------------------------------------------------------------------------
__device__ __forceinline__ uint32_t smem_u32(const void* p) {
    uint32_t a;
    asm("{ .reg .u64 t; cvta.to.shared.u64 t, %1; cvt.u32.u64 %0, t; }" : "=r"(a) : "l"(p));
    return a;
}
__device__ __forceinline__ void cpa16(uint32_t dst, const void* src) {
    asm volatile("cp.async.cg.shared.global [%0], [%1], 16;" :: "r"(dst), "l"(src));
}
#define CP_COMMIT() asm volatile("cp.async.commit_group;" ::: "memory")
#define CP_WAIT0()  asm volatile("cp.async.wait_group 0;" ::: "memory")

__device__ __forceinline__ uint32_t pack_h2(float lo, float hi) {
    __half2 h = __floats2half2_rn(lo, hi);
    return *reinterpret_cast<uint32_t*>(&h);
}
__device__ __forceinline__ void mma_f16(float (&c)[4], const uint32_t (&a)[4], const uint32_t (&b)[2]) {
    asm volatile(
        "mma.sync.aligned.m16n8k16.row.col.f32.f16.f16.f32 "
        "{%0,%1,%2,%3}, {%4,%5,%6,%7}, {%8,%9}, {%0,%1,%2,%3};\n"
        : "+f"(c[0]), "+f"(c[1]), "+f"(c[2]), "+f"(c[3])
        : "r"(a[0]), "r"(a[1]), "r"(a[2]), "r"(a[3]), "r"(b[0]), "r"(b[1]));
}
__device__ __forceinline__ void ldsm_x4(uint32_t& r0, uint32_t& r1, uint32_t& r2, uint32_t& r3,
                                        uint32_t addr) {
    asm volatile("ldmatrix.sync.aligned.m8n8.x4.shared.b16 {%0,%1,%2,%3}, [%4];"
        : "=r"(r0), "=r"(r1), "=r"(r2), "=r"(r3) : "r"(addr));
}

// ---------------------------------------------------------------------------
// Phase 0: convert weights to fp16; reset tile counter.
// ---------------------------------------------------------------------------
__global__ __launch_bounds__(256) void prep_kernel(const float* __restrict__ pw,
                                                   const float* __restrict__ bw)
{
    if (blockIdx.x == 0 && threadIdx.x == 0) g_tile_ctr = 0;
    const int stride = gridDim.x * blockDim.x;
    const int nTot = NSL * O * C / 4;
    const int nPw  = NE  * O * C / 4;
    for (int f = blockIdx.x * blockDim.x + threadIdx.x; f < nTot; f += stride) {
        float4 v = (f < nPw) ? ((const float4*)pw)[f] : ((const float4*)bw)[f - nPw];
        uint2 h;
        h.x = pack_h2(v.x, v.y);
        h.y = pack_h2(v.z, v.w);
        ((uint2*)g_wh)[f] = h;
    }
}

// ---------------------------------------------------------------------------
// Phase 1: GMM responsibilities. Block = 64 tokens, register-tiled projection.
// ---------------------------------------------------------------------------
__global__ __launch_bounds__(256) void resp_kernel(
    const float* __restrict__ x, const float* __restrict__ map_w,
    const float* __restrict__ map_b, const float* __restrict__ cent,
    const float* __restrict__ prior)
{
    __shared__ float xs[16][68];
    __shared__ float ws[16][68];
    __shared__ float s_k[64][65];
    __shared__ float s_cent[NE][RD];
    __shared__ float s_cc[NE], s_lp[NE], s_mb[RD];
    __shared__ float s_d[64];

    const int tid = threadIdx.x;
    const int t0 = blockIdx.x * 64;

    for (int i = tid; i < NE * RD; i += 256) s_cent[i / RD][i % RD] = cent[i];
    if (tid < NE) {
        float cc = 0.f;
        #pragma unroll
        for (int j = 0; j < RD; ++j) { float c = cent[tid * RD + j]; cc = fmaf(c, c, cc); }
        s_cc[tid] = cc;
        s_lp[tid] = logf(prior[tid]);
    }
    if (tid < RD) s_mb[tid] = map_b[tid];

    const int ty = tid >> 4, tx = tid & 15;
    const int lr = tid >> 2, lq = tid & 3;

    float acc[4][4];
    #pragma unroll
    for (int i = 0; i < 4; ++i)
        #pragma unroll
        for (int j = 0; j < 4; ++j) acc[i][j] = 0.f;

    for (int ct = 0; ct < C / 16; ++ct) {
        const float4 xv = *(const float4*)(x     + (size_t)(t0 + lr) * C + ct * 16 + lq * 4);
        const float4 wv = *(const float4*)(map_w + (size_t)lr        * C + ct * 16 + lq * 4);
        __syncthreads();
        xs[lq * 4 + 0][lr] = xv.x; xs[lq * 4 + 1][lr] = xv.y;
        xs[lq * 4 + 2][lr] = xv.z; xs[lq * 4 + 3][lr] = xv.w;
        ws[lq * 4 + 0][lr] = wv.x; ws[lq * 4 + 1][lr] = wv.y;
        ws[lq * 4 + 2][lr] = wv.z; ws[lq * 4 + 3][lr] = wv.w;
        __syncthreads();
        #pragma unroll
        for (int kk = 0; kk < 16; ++kk) {
            const float4 a = *(const float4*)&xs[kk][ty * 4];
            const float4 b = *(const float4*)&ws[kk][tx * 4];
            const float av[4] = {a.x, a.y, a.z, a.w};
            const float bv[4] = {b.x, b.y, b.z, b.w};
            #pragma unroll
            for (int i = 0; i < 4; ++i)
                #pragma unroll
                for (int j = 0; j < 4; ++j) acc[i][j] = fmaf(av[i], bv[j], acc[i][j]);
        }
    }
    __syncthreads();
    #pragma unroll
    for (int i = 0; i < 4; ++i)
        #pragma unroll
        for (int j = 0; j < 4; ++j)
            s_k[ty * 4 + i][tx * 4 + j] = acc[i][j] + s_mb[tx * 4 + j];
    __syncthreads();

    if (tid < 64) {
        float kk = 0.f, kc[NE];
        #pragma unroll
        for (int e = 0; e < NE; ++e) kc[e] = 0.f;
        #pragma unroll 8
        for (int j = 0; j < RD; ++j) {
            const float kj = s_k[tid][j];
            kk = fmaf(kj, kj, kk);
            #pragma unroll
            for (int e = 0; e < NE; ++e) kc[e] = fmaf(kj, s_cent[e][j], kc[e]);
        }
        const float LOG2PI = 1.8378770664093453f;
        float lr8[NE], m = -1e30f;
        #pragma unroll
        for (int e = 0; e < NE; ++e) {
            lr8[e] = -0.5f * (kk + s_cc[e] - 2.f * kc[e]) - (RD * 0.5f) * LOG2PI + s_lp[e];
            m = fmaxf(m, lr8[e]);
        }
        float s = 0.f;
        #pragma unroll
        for (int e = 0; e < NE; ++e) s += expf(lr8[e] - m);
        const float denom = m + logf(s);
        float4 r0, r1;
        r0.x = expf(lr8[0] - denom); r0.y = expf(lr8[1] - denom);
        r0.z = expf(lr8[2] - denom); r0.w = expf(lr8[3] - denom);
        r1.x = expf(lr8[4] - denom); r1.y = expf(lr8[5] - denom);
        r1.z = expf(lr8[6] - denom); r1.w = expf(lr8[7] - denom);
        const int tok = t0 + tid;
        *(float4*)&g_resp[tok * NE + 0] = r0;
        *(float4*)&g_resp[tok * NE + 4] = r1;
        s_d[tid] = denom;
    }
    __syncthreads();
    if (tid < 8) {                     // deterministic fixed-tree partial sum
        float a = 0.f;
        #pragma unroll
        for (int j = 0; j < 8; ++j) a += s_d[tid * 8 + j];
        s_d[tid] = a;
    }
    __syncthreads();
    if (tid == 0) {
        float a = 0.f;
        #pragma unroll
        for (int j = 0; j < 8; ++j) a += s_d[j];
        g_psum[blockIdx.x] = a;
    }
}

// ---------------------------------------------------------------------------
// Phase 2: persistent fp16 mma.sync GEMM.  y = A_big @ B_big^T + bias_b
//   Persistent CTAs + atomic tile counter kill wave quantization;
//   ldmatrix.x4 fragment loads; double-buffered cp.async B; on-the-fly A.
// ---------------------------------------------------------------------------
constexpr uint32_t OFF_RESP = 0;       // 128*8*4  = 4096
constexpr uint32_t OFF_BIAS = 4096;    // 256*4    = 1024
constexpr uint32_t OFF_A0   = 5120;    // 128*80   = 10240
constexpr uint32_t OFF_A1   = 15360;
constexpr uint32_t OFF_B0   = 25600;   // 256*80   = 20480
constexpr uint32_t OFF_B1   = 46080;
constexpr uint32_t SMEM_TOTAL = 66560;

__global__ __launch_bounds__(256, 1) void moe_gemm(
    const float* __restrict__ x, const float* __restrict__ bias_b,
    float* __restrict__ out)
{
    extern __shared__ __align__(128) char smem[];
    const uint32_t sb = smem_u32(smem);

    const int tid = threadIdx.x;
    const int warp = tid >> 5, lane = tid & 31;
    const int wm = warp >> 2, wn = warp & 3;       // 2 (M) x 4 (N); warp tile 64x64
    const int g = lane >> 2, tg = lane & 3;

    const int arow = tid >> 1;
    const int aseg = tid & 1;

    float* respS = (float*)(smem + OFF_RESP);
    float* biasS = (float*)(smem + OFF_BIAS);

    // per-lane ldmatrix address components (byte offsets into a tile buffer)
    const uint32_t aOff = (uint32_t)(wm * 64 + (lane & 15)) * 80 + (uint32_t)(lane >> 4) * 16;
    const uint32_t bOff = (uint32_t)(wn * 64 + (lane & 7)) * 80 + (uint32_t)(lane >> 3) * 16;

    __shared__ unsigned s_tile;

    for (;;) {
        __syncthreads();                        // smem quiesce between tiles
        if (tid == 0) s_tile = atomicAdd(&g_tile_ctr, 1u);
        __syncthreads();
        const unsigned t = s_tile;
        if (t >= NTILES) break;
        const int bm = t >> 1, bn = t & 1;

        // preload resp tile + bias_b slice
        ((float4*)respS)[tid] = ((const float4*)(g_resp + (size_t)bm * BM * NE))[tid];
        if (tid < 64) ((float4*)biasS)[tid] = ((const float4*)(bias_b + bn * BN))[tid];

        float4 xv[4];
        auto ldgX = [&](int i0c) {
            const float4* p = (const float4*)(x + (size_t)(bm * BM + arow) * C + i0c + aseg * 16);
            xv[0] = p[0]; xv[1] = p[1]; xv[2] = p[2]; xv[3] = p[3];
        };
        auto stsA = [&](int e, uint32_t offA) {
            const float s = (e < NE) ? respS[arow * NE + e] : 1.0f;
            uint4 h0, h1;
            h0.x = pack_h2(xv[0].x * s, xv[0].y * s);
            h0.y = pack_h2(xv[0].z * s, xv[0].w * s);
            h0.z = pack_h2(xv[1].x * s, xv[1].y * s);
            h0.w = pack_h2(xv[1].z * s, xv[1].w * s);
            h1.x = pack_h2(xv[2].x * s, xv[2].y * s);
            h1.y = pack_h2(xv[2].z * s, xv[2].w * s);
            h1.z = pack_h2(xv[3].x * s, xv[3].y * s);
            h1.w = pack_h2(xv[3].z * s, xv[3].w * s);
            uint4* dst = (uint4*)(smem + offA + arow * 80 + aseg * 32);
            dst[0] = h0; dst[1] = h1;
        };
        auto issueB = [&](int e, int i0c, uint32_t offB) {
            const __half* base = g_wh + ((size_t)e * O + bn * BN) * C + i0c;
            #pragma unroll
            for (int k = 0; k < 4; ++k) {
                const int c = tid + k * 256;
                const int row = c >> 2, q = c & 3;
                cpa16(sb + offB + row * 80 + q * 16, base + (size_t)row * C + q * 8);
            }
        };

        float acc[4][8][4];
        #pragma unroll
        for (int a = 0; a < 4; ++a)
            #pragma unroll
            for (int b = 0; b < 8; ++b)
                #pragma unroll
                for (int c = 0; c < 4; ++c) acc[a][b][c] = 0.f;

        ldgX(0);
        issueB(0, 0, OFF_B0);
        CP_COMMIT();
        __syncthreads();           // resp/bias visible
        stsA(0, OFF_A0);
        CP_WAIT0();
        __syncthreads();

        for (int kt = 0; kt < NKT; ++kt) {
            const int s = kt & 1;
            const bool more = (kt + 1 < NKT);
            int e1 = 0;
            if (more) {
                e1 = (kt + 1) % NSL;
                const int i1 = ((kt + 1) / NSL) * BK;
                issueB(e1, i1, s ? OFF_B0 : OFF_B1);
                CP_COMMIT();
                if (e1 == 0) ldgX(i1);
            }

            // ---- fragment loads via ldmatrix, then 64 MMAs ----
            {
                const uint32_t A0 = sb + (s ? OFF_A1 : OFF_A0);
                const uint32_t B0 = sb + (s ? OFF_B1 : OFF_B0);
                uint32_t af[2][4][4], bf[2][8][2];
                #pragma unroll
                for (int mt = 0; mt < 4; ++mt) {
                    ldsm_x4(af[0][mt][0], af[0][mt][1], af[0][mt][2], af[0][mt][3],
                            A0 + aOff + mt * 1280);
                    ldsm_x4(af[1][mt][0], af[1][mt][1], af[1][mt][2], af[1][mt][3],
                            A0 + aOff + mt * 1280 + 32);
                }
                #pragma unroll
                for (int nt = 0; nt < 8; ++nt) {
                    uint32_t r0, r1, r2, r3;
                    ldsm_x4(r0, r1, r2, r3, B0 + bOff + nt * 640);
                    bf[0][nt][0] = r0; bf[0][nt][1] = r1;
                    bf[1][nt][0] = r2; bf[1][nt][1] = r3;
                }
                #pragma unroll
                for (int ks = 0; ks < 2; ++ks)
                    #pragma unroll
                    for (int mt = 0; mt < 4; ++mt)
                        #pragma unroll
                        for (int nt = 0; nt < 8; ++nt)
                            mma_f16(acc[mt][nt], af[ks][mt], bf[ks][nt]);
            }

            if (more) {
                stsA(e1, s ? OFF_A0 : OFF_A1);
                CP_WAIT0();
            }
            __syncthreads();
        }

        // epilogue: + bias_b, store float2 pairs
        #pragma unroll
        for (int mt = 0; mt < 4; ++mt) {
            const int row = bm * BM + wm * 64 + mt * 16 + g;
            #pragma unroll
            for (int nt = 0; nt < 8; ++nt) {
                const int cb = wn * 64 + nt * 8 + tg * 2;
                const float b0 = biasS[cb], b1 = biasS[cb + 1];
                float2 v0 = make_float2(acc[mt][nt][0] + b0, acc[mt][nt][1] + b1);
                float2 v1 = make_float2(acc[mt][nt][2] + b0, acc[mt][nt][3] + b1);
                float* dst = out + (size_t)row * O + bn * BN + cb;
                *(float2*)dst = v0;
                *(float2*)(dst + 8 * O) = v1;
            }
        }
    }
}

// ---------------------------------------------------------------------------
// Phase 3: loss = -COMMIT * sum(partials)
// ---------------------------------------------------------------------------
__global__ __launch_bounds__(256) void loss_kernel(float* __restrict__ out, int out_size)
{
    __shared__ float s[256];
    const int tid = threadIdx.x;
    s[tid] = g_psum[tid];              // exactly 256 partials
    __syncthreads();
    for (int w = 128; w > 0; w >>= 1) {
        if (tid < w) s[tid] += s[tid + w];
        __syncthreads();
    }
    if (tid == 0) {
        const float loss = -0.1f * s[0];
        for (long i = (long)N_TOK * O; i < out_size; ++i) out[i] = loss;
    }
}

// ---------------------------------------------------------------------------
extern "C" void kernel_launch(void* const* d_in, const int* in_sizes, int n_in,
                              void* d_out, int out_size)
{
    const float* x      = (const float*)d_in[0];
    // d_in[1] = key_feat, ignored by the forward pass
    const float* map_w  = (const float*)d_in[2];
    const float* map_b  = (const float*)d_in[3];
    const float* cent   = (const float*)d_in[4];
    const float* prior  = (const float*)d_in[5];
    const float* pw_w   = (const float*)d_in[6];
    const float* bias_w = (const float*)d_in[7];
    const float* bias_b = (const float*)d_in[8];
    float* out = (float*)d_out;

    cudaFuncSetAttribute(moe_gemm, cudaFuncAttributeMaxDynamicSharedMemorySize, SMEM_TOTAL);

    prep_kernel<<<576, 256>>>(pw_w, bias_w);
    resp_kernel<<<N_TOK / 64, 256>>>(x, map_w, map_b, cent, prior);
    moe_gemm<<<152, 256, SMEM_TOTAL>>>(x, bias_b, out);   // persistent, 1 CTA/SM
    loss_kernel<<<1, 256>>>(out, out_size);
}

// round 10
// speedup vs baseline: 3.2169x; 1.5823x over previous
#include <cuda_runtime.h>
#include <cuda_fp16.h>
#include <cstdint>

// ---------------------------------------------------------------------------
// Problem constants
// ---------------------------------------------------------------------------
constexpr int N_TOK = 16384;   // T*B
constexpr int C     = 512;
constexpr int O     = 512;
constexpr int RD    = 64;
constexpr int NE    = 8;
constexpr int NSL   = NE + 1;          // 8 expert slices + bias slice
constexpr int BM = 128, BN = 256;
constexpr unsigned NTILES = (N_TOK / BM) * (O / BN);   // 256

// Legacy path tiling
constexpr int BK_LG  = 32;
constexpr int NKT_LG = NSL * (C / BK_LG);   // 144
// tcgen05 path tiling
constexpr int BK_TC  = 64;
constexpr int NKT_TC = NSL * C / BK_TC;     // 72

// Scratch (static device globals — no allocation)
__device__ float g_resp[N_TOK * NE];
__device__ float g_psum[N_TOK / 64];                 // 256 per-block denom sums
__device__ __align__(16) __half g_wh[NSL * O * C];   // fp16 weights: experts 0..7, then bias_w
__device__ unsigned g_tile_ctr;

// ---------------------------------------------------------------------------
// Arch-specific gate: tcgen05 only exists in the sm_103a/sm_103f cubin pass.
// The plain compute_103 PTX pass compiles the legacy mma.sync body instead.
// ---------------------------------------------------------------------------
#if defined(__CUDA_ARCH_FEAT_SM103_ALL) || defined(__CUDA_ARCH_FEAT_SM100_ALL) || \
    defined(__CUDA_ARCH_SPECIFIC__) || defined(__CUDA_ARCH_FAMILY_SPECIFIC__)
#define USE_TC 1
#endif

// ---------------------------------------------------------------------------
// Common helpers
// ---------------------------------------------------------------------------
__device__ __forceinline__ uint32_t smem_u32(const void* p) {
    uint32_t a;
    asm("{ .reg .u64 t; cvta.to.shared.u64 t, %1; cvt.u32.u64 %0, t; }" : "=r"(a) : "l"(p));
    return a;
}
__device__ __forceinline__ void cpa16(uint32_t dst, const void* src) {
    asm volatile("cp.async.cg.shared.global [%0], [%1], 16;" :: "r"(dst), "l"(src));
}
#define CP_COMMIT() asm volatile("cp.async.commit_group;" ::: "memory")
#define CP_WAIT0()  asm volatile("cp.async.wait_group 0;" ::: "memory")
#define CP_WAIT1()  asm volatile("cp.async.wait_group 1;" ::: "memory")

__device__ __forceinline__ uint32_t pack_h2(float lo, float hi) {
    __half2 h = __floats2half2_rn(lo, hi);
    return *reinterpret_cast<uint32_t*>(&h);
}
__device__ __forceinline__ uint32_t swz(uint32_t off) {   // SW128: Swizzle<3,4,3>
    return off ^ ((off >> 3) & 0x70);
}

// ---- legacy mma.sync helpers ----
__device__ __forceinline__ void mma_f16(float (&c)[4], const uint32_t (&a)[4], const uint32_t (&b)[2]) {
    asm volatile(
        "mma.sync.aligned.m16n8k16.row.col.f32.f16.f16.f32 "
        "{%0,%1,%2,%3}, {%4,%5,%6,%7}, {%8,%9}, {%0,%1,%2,%3};\n"
        : "+f"(c[0]), "+f"(c[1]), "+f"(c[2]), "+f"(c[3])
        : "r"(a[0]), "r"(a[1]), "r"(a[2]), "r"(a[3]), "r"(b[0]), "r"(b[1]));
}
__device__ __forceinline__ void ldsm_x4(uint32_t& r0, uint32_t& r1, uint32_t& r2, uint32_t& r3,
                                        uint32_t addr) {
    asm volatile("ldmatrix.sync.aligned.m8n8.x4.shared.b16 {%0,%1,%2,%3}, [%4];"
        : "=r"(r0), "=r"(r1), "=r"(r2), "=r"(r3) : "r"(addr));
}

// ---- tcgen05 helpers (compiled only in the arch-specific pass) ----
#ifdef USE_TC
#define FENCE_ASYNC() asm volatile("fence.proxy.async.shared::cta;" ::: "memory")
__device__ __forceinline__ void mbar_init(uint32_t a, uint32_t cnt) {
    asm volatile("mbarrier.init.shared.b64 [%0], %1;" :: "r"(a), "r"(cnt) : "memory");
}
__device__ __forceinline__ void mbar_wait(uint32_t a, uint32_t parity) {
    asm volatile(
        "{\n\t.reg .pred P;\n\t"
        "W_%=:\n\t"
        "mbarrier.try_wait.parity.shared::cta.b64 P, [%0], %1, 0x989680;\n\t"
        "@P bra.uni D_%=;\n\t"
        "bra.uni W_%=;\n\t"
        "D_%=:\n\t}"
        :: "r"(a), "r"(parity) : "memory");
}
__device__ __forceinline__ uint32_t elect1() {
    uint32_t p;
    asm volatile("{ .reg .pred q; elect.sync _|q, 0xFFFFFFFF; selp.b32 %0, 1, 0, q; }" : "=r"(p));
    return p;
}
__device__ __forceinline__ void tcommit(uint32_t bar) {
    asm volatile(
        "tcgen05.commit.cta_group::1.mbarrier::arrive::one.shared::cluster.b64 [%0];"
        :: "r"(bar) : "memory");
}
__device__ __forceinline__ void mma_f16_ss(uint32_t d, uint64_t da, uint64_t db,
                                           uint32_t idesc, uint32_t en) {
    asm volatile(
        "{\n\t.reg .pred p;\n\t"
        "setp.ne.u32 p, %4, 0;\n\t"
        "tcgen05.mma.cta_group::1.kind::f16 [%0], %1, %2, %3, {%5, %5, %5, %5}, p;\n\t"
        "}"
        :: "r"(d), "l"(da), "l"(db), "r"(idesc), "r"(en), "r"(0u) : "memory");
}
#define TM_ALLOC(sm, n)   asm volatile("tcgen05.alloc.cta_group::1.sync.aligned.shared::cta.b32 [%0], %1;" :: "r"(sm), "r"((uint32_t)(n)) : "memory")
#define TM_RELINQ()       asm volatile("tcgen05.relinquish_alloc_permit.cta_group::1.sync.aligned;")
#define TM_DEALLOC(t, n)  asm volatile("tcgen05.dealloc.cta_group::1.sync.aligned.b32 %0, %1;" :: "r"(t), "r"((uint32_t)(n)))
#define TM_FENCE_AFTER()  asm volatile("tcgen05.fence::after_thread_sync;" ::: "memory")
#define TM_FENCE_BEFORE() asm volatile("tcgen05.fence::before_thread_sync;" ::: "memory")
#define TM_WAIT_LD()      asm volatile("tcgen05.wait::ld.sync.aligned;" ::: "memory")
#define TM_LD_X32(r, addr) \
    asm volatile( \
        "tcgen05.ld.sync.aligned.32x32b.x32.b32 " \
        "{%0, %1, %2, %3, %4, %5, %6, %7, " \
        " %8, %9, %10, %11, %12, %13, %14, %15, " \
        " %16, %17, %18, %19, %20, %21, %22, %23, " \
        " %24, %25, %26, %27, %28, %29, %30, %31}, [%32];" \
        : "=r"((r)[0]),  "=r"((r)[1]),  "=r"((r)[2]),  "=r"((r)[3]), \
          "=r"((r)[4]),  "=r"((r)[5]),  "=r"((r)[6]),  "=r"((r)[7]), \
          "=r"((r)[8]),  "=r"((r)[9]),  "=r"((r)[10]), "=r"((r)[11]), \
          "=r"((r)[12]), "=r"((r)[13]), "=r"((r)[14]), "=r"((r)[15]), \
          "=r"((r)[16]), "=r"((r)[17]), "=r"((r)[18]), "=r"((r)[19]), \
          "=r"((r)[20]), "=r"((r)[21]), "=r"((r)[22]), "=r"((r)[23]), \
          "=r"((r)[24]), "=r"((r)[25]), "=r"((r)[26]), "=r"((r)[27]), \
          "=r"((r)[28]), "=r"((r)[29]), "=r"((r)[30]), "=r"((r)[31]) \
        : "r"(addr))

// SMEM desc: SW128, version=1, SBO=64, LBO=1 (K-major 128B rows)
constexpr uint64_t DESC_BASE =
    (uint64_t(2) << 61) | (uint64_t(1) << 46) | (uint64_t(64) << 32) | (uint64_t(1) << 16);
__device__ __forceinline__ uint64_t make_desc(uint32_t addr) {
    return DESC_BASE | ((uint64_t)(addr >> 4) & 0x3FFF);
}
// idesc kind::f16: dtype=F32 (1<<4), atype=btype=F16 (0), N=256 -> 32<<17, M=128 -> 8<<24
constexpr uint32_t IDESC_F16 = (1u << 4) | (32u << 17) | (8u << 24);
#endif  // USE_TC

// ---------------------------------------------------------------------------
// SMEM layout (host-visible constants; sized for the larger tcgen05 path)
// ---------------------------------------------------------------------------
constexpr uint32_t OFF_RESP = 0;        // 4096
constexpr uint32_t OFF_BIAS = 4096;     // 1024
constexpr uint32_t OFF_TM   = 5120;     // 8  (tmem ptr)
constexpr uint32_t OFF_BARS = 5128;     // 16 (2 mbarriers)
// tcgen05 tiles (1024-aligned)
constexpr uint32_t TC_A0 = 8192;        // 128*128B = 16 KB
constexpr uint32_t TC_A1 = 24576;
constexpr uint32_t TC_B0 = 40960;       // 256*128B = 32 KB
constexpr uint32_t TC_B1 = 73728;
constexpr uint32_t TC_END = 106496;
// legacy tiles (80B pitch)
constexpr uint32_t LG_A0 = 5248;        // 128*80 = 10240
constexpr uint32_t LG_A1 = 15488;
constexpr uint32_t LG_B0 = 25728;       // 256*80 = 20480
constexpr uint32_t LG_B1 = 46208;       // end 66688
constexpr uint32_t SMEM_TOTAL = TC_END + 1024;   // + alignment slack

// ---------------------------------------------------------------------------
// Phase 1 (fused): blocks [0,256) = GMM responsibilities (64 tokens each);
//                  blocks [256,368) = weight fp16 conversion; ctr reset.
// ---------------------------------------------------------------------------
__global__ __launch_bounds__(256) void prelude_kernel(
    const float* __restrict__ x, const float* __restrict__ map_w,
    const float* __restrict__ map_b, const float* __restrict__ cent,
    const float* __restrict__ prior,
    const float* __restrict__ pw, const float* __restrict__ bw)
{
    const int tid = threadIdx.x;

    if (blockIdx.x >= 256) {      // ---- weight conversion ----
        if (blockIdx.x == 256 && tid == 0) g_tile_ctr = 0;
        const int nTot = NSL * O * C / 4;
        const int nPw  = NE  * O * C / 4;
        const int stride = 112 * 256;
        for (int f = (blockIdx.x - 256) * 256 + tid; f < nTot; f += stride) {
            float4 v = (f < nPw) ? ((const float4*)pw)[f] : ((const float4*)bw)[f - nPw];
            uint2 h;
            h.x = pack_h2(v.x, v.y);
            h.y = pack_h2(v.z, v.w);
            ((uint2*)g_wh)[f] = h;
        }
        return;
    }

    // ---- responsibilities ----
    __shared__ float xs[16][68];
    __shared__ float ws[16][68];
    __shared__ float s_k[64][65];
    __shared__ float s_cent[NE][RD];
    __shared__ float s_cc[NE], s_lp[NE], s_mb[RD];
    __shared__ float s_d[64];

    const int t0 = blockIdx.x * 64;

    for (int i = tid; i < NE * RD; i += 256) s_cent[i / RD][i % RD] = cent[i];
    if (tid < NE) {
        float cc = 0.f;
        #pragma unroll
        for (int j = 0; j < RD; ++j) { float c = cent[tid * RD + j]; cc = fmaf(c, c, cc); }
        s_cc[tid] = cc;
        s_lp[tid] = logf(prior[tid]);
    }
    if (tid < RD) s_mb[tid] = map_b[tid];

    const int ty = tid >> 4, tx = tid & 15;
    const int lr = tid >> 2, lq = tid & 3;

    float acc[4][4];
    #pragma unroll
    for (int i = 0; i < 4; ++i)
        #pragma unroll
        for (int j = 0; j < 4; ++j) acc[i][j] = 0.f;

    for (int ct = 0; ct < C / 16; ++ct) {
        const float4 xv = *(const float4*)(x     + (size_t)(t0 + lr) * C + ct * 16 + lq * 4);
        const float4 wv = *(const float4*)(map_w + (size_t)lr        * C + ct * 16 + lq * 4);
        __syncthreads();
        xs[lq * 4 + 0][lr] = xv.x; xs[lq * 4 + 1][lr] = xv.y;
        xs[lq * 4 + 2][lr] = xv.z; xs[lq * 4 + 3][lr] = xv.w;
        ws[lq * 4 + 0][lr] = wv.x; ws[lq * 4 + 1][lr] = wv.y;
        ws[lq * 4 + 2][lr] = wv.z; ws[lq * 4 + 3][lr] = wv.w;
        __syncthreads();
        #pragma unroll
        for (int kk = 0; kk < 16; ++kk) {
            const float4 a = *(const float4*)&xs[kk][ty * 4];
            const float4 b = *(const float4*)&ws[kk][tx * 4];
            const float av[4] = {a.x, a.y, a.z, a.w};
            const float bv[4] = {b.x, b.y, b.z, b.w};
            #pragma unroll
            for (int i = 0; i < 4; ++i)
                #pragma unroll
                for (int j = 0; j < 4; ++j) acc[i][j] = fmaf(av[i], bv[j], acc[i][j]);
        }
    }
    __syncthreads();
    #pragma unroll
    for (int i = 0; i < 4; ++i)
        #pragma unroll
        for (int j = 0; j < 4; ++j)
            s_k[ty * 4 + i][tx * 4 + j] = acc[i][j] + s_mb[tx * 4 + j];
    __syncthreads();

    if (tid < 64) {
        float kk = 0.f, kc[NE];
        #pragma unroll
        for (int e = 0; e < NE; ++e) kc[e] = 0.f;
        #pragma unroll 8
        for (int j = 0; j < RD; ++j) {
            const float kj = s_k[tid][j];
            kk = fmaf(kj, kj, kk);
            #pragma unroll
            for (int e = 0; e < NE; ++e) kc[e] = fmaf(kj, s_cent[e][j], kc[e]);
        }
        const float LOG2PI = 1.8378770664093453f;
        float lr8[NE], m = -1e30f;
        #pragma unroll
        for (int e = 0; e < NE; ++e) {
            lr8[e] = -0.5f * (kk + s_cc[e] - 2.f * kc[e]) - (RD * 0.5f) * LOG2PI + s_lp[e];
            m = fmaxf(m, lr8[e]);
        }
        float s = 0.f;
        #pragma unroll
        for (int e = 0; e < NE; ++e) s += expf(lr8[e] - m);
        const float denom = m + logf(s);
        float4 r0, r1;
        r0.x = expf(lr8[0] - denom); r0.y = expf(lr8[1] - denom);
        r0.z = expf(lr8[2] - denom); r0.w = expf(lr8[3] - denom);
        r1.x = expf(lr8[4] - denom); r1.y = expf(lr8[5] - denom);
        r1.z = expf(lr8[6] - denom); r1.w = expf(lr8[7] - denom);
        const int tok = t0 + tid;
        *(float4*)&g_resp[tok * NE + 0] = r0;
        *(float4*)&g_resp[tok * NE + 4] = r1;
        s_d[tid] = denom;
    }
    __syncthreads();
    if (tid < 8) {
        float a = 0.f;
        #pragma unroll
        for (int j = 0; j < 8; ++j) a += s_d[tid * 8 + j];
        s_d[tid] = a;
    }
    __syncthreads();
    if (tid == 0) {
        float a = 0.f;
        #pragma unroll
        for (int j = 0; j < 8; ++j) a += s_d[j];
        g_psum[blockIdx.x] = a;
    }
}

// ---------------------------------------------------------------------------
// Phase 2: persistent GEMM + fused loss.  y = A_big @ B_big^T + bias_b
//   tcgen05 kind::f16 path in the sm_103a cubin; legacy mma.sync fallback.
// ---------------------------------------------------------------------------
__global__ __launch_bounds__(256, 1) void moe_gemm(
    const float* __restrict__ x, const float* __restrict__ bias_b,
    float* __restrict__ out, int out_size)
{
    extern __shared__ __align__(128) char smem_raw[];
    const uint32_t sb_raw = smem_u32(smem_raw);
    const uint32_t pad = (1024u - (sb_raw & 1023u)) & 1023u;
    char* smem = smem_raw + pad;
    const uint32_t sb = sb_raw + pad;

    const int tid = threadIdx.x;
    const int warp = tid >> 5, lane = tid & 31;

    float* respS = (float*)(smem + OFF_RESP);
    float* biasS = (float*)(smem + OFF_BIAS);
    __shared__ unsigned s_tile;
    __shared__ float s_red[256];

#ifdef USE_TC
    // =================== tcgen05 path ===================
    if (warp == 0) { TM_ALLOC(sb + OFF_TM, 256); TM_RELINQ(); }
    if (tid == 0) { mbar_init(sb + OFF_BARS, 1); mbar_init(sb + OFF_BARS + 8, 1); }
    __syncthreads();
    uint32_t tmem;
    asm volatile("ld.shared.b32 %0, [%1];" : "=r"(tmem) : "r"(sb + OFF_TM));

    const int arow = tid >> 1;          // A row this thread builds
    const int aseg = tid & 1;           // 64-byte half of the 128B row

    for (;;) {
        __syncthreads();
        if (tid == 0) s_tile = atomicAdd(&g_tile_ctr, 1u);
        __syncthreads();
        const unsigned t = s_tile;
        if (t > NTILES) break;
        if (t == NTILES) {              // ---- fused loss tile ----
            s_red[tid] = g_psum[tid];
            __syncthreads();
            for (int w = 128; w > 0; w >>= 1) {
                if (tid < w) s_red[tid] += s_red[tid + w];
                __syncthreads();
            }
            if (tid == 0) {
                const float loss = -0.1f * s_red[0];
                for (long i = (long)N_TOK * O; i < out_size; ++i) out[i] = loss;
            }
            continue;
        }
        const int bm = t >> 1, bn = t & 1;

        ((float4*)respS)[tid] = ((const float4*)(g_resp + (size_t)bm * BM * NE))[tid];
        if (tid < 64) ((float4*)biasS)[tid] = ((const float4*)(bias_b + bn * BN))[tid];

        float4 xv[8];                   // 32 x-floats: row arow, cols [aseg*32, +32)
        auto ldgX = [&](int i0c) {
            const float4* p = (const float4*)(x + (size_t)(bm * BM + arow) * C + i0c + aseg * 32);
            #pragma unroll
            for (int q = 0; q < 8; ++q) xv[q] = p[q];
        };
        auto stsA = [&](int e, uint32_t offA) {
            const float s = (e < NE) ? respS[arow * NE + e] : 1.0f;
            #pragma unroll
            for (int q = 0; q < 4; ++q) {
                uint4 h;
                h.x = pack_h2(xv[q * 2].x * s,     xv[q * 2].y * s);
                h.y = pack_h2(xv[q * 2].z * s,     xv[q * 2].w * s);
                h.z = pack_h2(xv[q * 2 + 1].x * s, xv[q * 2 + 1].y * s);
                h.w = pack_h2(xv[q * 2 + 1].z * s, xv[q * 2 + 1].w * s);
                *(uint4*)(smem + offA + swz(arow * 128 + aseg * 64 + q * 16)) = h;
            }
        };
        auto issueB = [&](int e, int i0c, uint32_t offB) {
            const __half* base = g_wh + ((size_t)e * O + bn * BN) * C + i0c;
            #pragma unroll
            for (int it = 0; it < 8; ++it) {
                const int f = tid + it * 256;
                const int row = f >> 3, q = f & 7;
                cpa16(sb + offB + swz(row * 128 + q * 16), base + (size_t)row * C + q * 8);
            }
        };

        // prologue: buffer 0 = kt 0
        ldgX(0);
        issueB(0, 0, TC_B0);
        CP_COMMIT();
        __syncthreads();               // resp/bias visible
        stsA(0, TC_A0);

        const uint64_t dA[2] = { make_desc(sb + TC_A0), make_desc(sb + TC_A1) };
        const uint64_t dB[2] = { make_desc(sb + TC_B0), make_desc(sb + TC_B1) };

        for (int kt = 0; kt < NKT_TC; ++kt) {
            const int s = kt & 1;
            if (kt + 1 < NKT_TC) {
                if (kt >= 1) mbar_wait(sb + OFF_BARS + 8 * (s ^ 1), ((kt - 1) >> 1) & 1);
                const int e1 = (kt + 1) % NSL;
                const int i1 = ((kt + 1) / NSL) * BK_TC;
                issueB(e1, i1, s ? TC_B0 : TC_B1);
                CP_COMMIT();
                if (e1 == 0) ldgX(i1);
                stsA(e1, s ? TC_A0 : TC_A1);
                CP_WAIT1();
            } else {
                CP_WAIT0();
            }
            FENCE_ASYNC();
            __syncthreads();

            if (warp == 0 && elect1()) {
                #pragma unroll
                for (int k = 0; k < 4; ++k) {
                    const uint32_t en = (kt | k) ? 1u : 0u;
                    mma_f16_ss(tmem, dA[s] + k * 2, dB[s] + k * 2, IDESC_F16, en);
                }
                tcommit(sb + OFF_BARS + 8 * s);
            }
        }

        // final commit: bar[(NKT_TC-1)&1]=bar1, 36th commit -> parity 1
        mbar_wait(sb + OFF_BARS + 8 * ((NKT_TC - 1) & 1), ((NKT_TC - 1) >> 1) & 1);
        TM_FENCE_AFTER();

        if (warp < 4) {
            const int row = bm * BM + warp * 32 + lane;
            float* dst = out + (size_t)row * O + bn * BN;
            #pragma unroll 1
            for (int c = 0; c < 8; ++c) {
                uint32_t r[32];
                TM_LD_X32(r, tmem + c * 32);
                TM_WAIT_LD();
                #pragma unroll
                for (int q = 0; q < 8; ++q) {
                    const float4 bb = *(const float4*)&biasS[c * 32 + q * 4];
                    float4 v;
                    v.x = __uint_as_float(r[q * 4 + 0]) + bb.x;
                    v.y = __uint_as_float(r[q * 4 + 1]) + bb.y;
                    v.z = __uint_as_float(r[q * 4 + 2]) + bb.z;
                    v.w = __uint_as_float(r[q * 4 + 3]) + bb.w;
                    *(float4*)(dst + c * 32 + q * 4) = v;
                }
            }
            TM_FENCE_BEFORE();
        }
    }
    __syncthreads();
    if (warp == 0) TM_DEALLOC(tmem, 256);

#else
    // =================== legacy mma.sync fallback (R8-proven) ===================
    const int wm = warp >> 2, wn = warp & 3;
    const int g = lane >> 2, tg = lane & 3;
    const int arow = tid >> 1;
    const int aseg = tid & 1;

    const uint32_t aOff = (uint32_t)(wm * 64 + (lane & 15)) * 80 + (uint32_t)(lane >> 4) * 16;
    const uint32_t bOff = (uint32_t)(wn * 64 + (lane & 7)) * 80 + (uint32_t)(lane >> 3) * 16;

    for (;;) {
        __syncthreads();
        if (tid == 0) s_tile = atomicAdd(&g_tile_ctr, 1u);
        __syncthreads();
        const unsigned t = s_tile;
        if (t > NTILES) break;
        if (t == NTILES) {
            s_red[tid] = g_psum[tid];
            __syncthreads();
            for (int w = 128; w > 0; w >>= 1) {
                if (tid < w) s_red[tid] += s_red[tid + w];
                __syncthreads();
            }
            if (tid == 0) {
                const float loss = -0.1f * s_red[0];
                for (long i = (long)N_TOK * O; i < out_size; ++i) out[i] = loss;
            }
            continue;
        }
        const int bm = t >> 1, bn = t & 1;

        ((float4*)respS)[tid] = ((const float4*)(g_resp + (size_t)bm * BM * NE))[tid];
        if (tid < 64) ((float4*)biasS)[tid] = ((const float4*)(bias_b + bn * BN))[tid];

        float4 xv[4];
        auto ldgX = [&](int i0c) {
            const float4* p = (const float4*)(x + (size_t)(bm * BM + arow) * C + i0c + aseg * 16);
            xv[0] = p[0]; xv[1] = p[1]; xv[2] = p[2]; xv[3] = p[3];
        };
        auto stsA = [&](int e, uint32_t offA) {
            const float s = (e < NE) ? respS[arow * NE + e] : 1.0f;
            uint4 h0, h1;
            h0.x = pack_h2(xv[0].x * s, xv[0].y * s);
            h0.y = pack_h2(xv[0].z * s, xv[0].w * s);
            h0.z = pack_h2(xv[1].x * s, xv[1].y * s);
            h0.w = pack_h2(xv[1].z * s, xv[1].w * s);
            h1.x = pack_h2(xv[2].x * s, xv[2].y * s);
            h1.y = pack_h2(xv[2].z * s, xv[2].w * s);
            h1.z = pack_h2(xv[3].x * s, xv[3].y * s);
            h1.w = pack_h2(xv[3].z * s, xv[3].w * s);
            uint4* dst = (uint4*)(smem + offA + arow * 80 + aseg * 32);
            dst[0] = h0; dst[1] = h1;
        };
        auto issueB = [&](int e, int i0c, uint32_t offB) {
            const __half* base = g_wh + ((size_t)e * O + bn * BN) * C + i0c;
            #pragma unroll
            for (int k = 0; k < 4; ++k) {
                const int c = tid + k * 256;
                const int row = c >> 2, q = c & 3;
                cpa16(sb + offB + row * 80 + q * 16, base + (size_t)row * C + q * 8);
            }
        };

        float acc[4][8][4];
        #pragma unroll
        for (int a = 0; a < 4; ++a)
            #pragma unroll
            for (int b = 0; b < 8; ++b)
                #pragma unroll
                for (int c = 0; c < 4; ++c) acc[a][b][c] = 0.f;

        ldgX(0);
        issueB(0, 0, LG_B0);
        CP_COMMIT();
        __syncthreads();
        stsA(0, LG_A0);
        CP_WAIT0();
        __syncthreads();

        for (int kt = 0; kt < NKT_LG; ++kt) {
            const int s = kt & 1;
            const bool more = (kt + 1 < NKT_LG);
            int e1 = 0;
            if (more) {
                e1 = (kt + 1) % NSL;
                const int i1 = ((kt + 1) / NSL) * BK_LG;
                issueB(e1, i1, s ? LG_B0 : LG_B1);
                CP_COMMIT();
                if (e1 == 0) ldgX(i1);
            }
            {
                const uint32_t A0 = sb + (s ? LG_A1 : LG_A0);
                const uint32_t B0 = sb + (s ? LG_B1 : LG_B0);
                uint32_t af[2][4][4], bf[2][8][2];
                #pragma unroll
                for (int mt = 0; mt < 4; ++mt) {
                    ldsm_x4(af[0][mt][0], af[0][mt][1], af[0][mt][2], af[0][mt][3],
                            A0 + aOff + mt * 1280);
                    ldsm_x4(af[1][mt][0], af[1][mt][1], af[1][mt][2], af[1][mt][3],
                            A0 + aOff + mt * 1280 + 32);
                }
                #pragma unroll
                for (int nt = 0; nt < 8; ++nt) {
                    uint32_t r0, r1, r2, r3;
                    ldsm_x4(r0, r1, r2, r3, B0 + bOff + nt * 640);
                    bf[0][nt][0] = r0; bf[0][nt][1] = r1;
                    bf[1][nt][0] = r2; bf[1][nt][1] = r3;
                }
                #pragma unroll
                for (int ks = 0; ks < 2; ++ks)
                    #pragma unroll
                    for (int mt = 0; mt < 4; ++mt)
                        #pragma unroll
                        for (int nt = 0; nt < 8; ++nt)
                            mma_f16(acc[mt][nt], af[ks][mt], bf[ks][nt]);
            }
            if (more) {
                stsA(e1, s ? LG_A0 : LG_A1);
                CP_WAIT0();
            }
            __syncthreads();
        }

        #pragma unroll
        for (int mt = 0; mt < 4; ++mt) {
            const int row = bm * BM + wm * 64 + mt * 16 + g;
            #pragma unroll
            for (int nt = 0; nt < 8; ++nt) {
                const int cb = wn * 64 + nt * 8 + tg * 2;
                const float b0 = biasS[cb], b1 = biasS[cb + 1];
                float2 v0 = make_float2(acc[mt][nt][0] + b0, acc[mt][nt][1] + b1);
                float2 v1 = make_float2(acc[mt][nt][2] + b0, acc[mt][nt][3] + b1);
                float* dst = out + (size_t)row * O + bn * BN + cb;
                *(float2*)dst = v0;
                *(float2*)(dst + 8 * O) = v1;
            }
        }
    }
#endif
}

// ---------------------------------------------------------------------------
extern "C" void kernel_launch(void* const* d_in, const int* in_sizes, int n_in,
                              void* d_out, int out_size)
{
    const float* x      = (const float*)d_in[0];
    // d_in[1] = key_feat, ignored by the forward pass
    const float* map_w  = (const float*)d_in[2];
    const float* map_b  = (const float*)d_in[3];
    const float* cent   = (const float*)d_in[4];
    const float* prior  = (const float*)d_in[5];
    const float* pw_w   = (const float*)d_in[6];
    const float* bias_w = (const float*)d_in[7];
    const float* bias_b = (const float*)d_in[8];
    float* out = (float*)d_out;

    cudaFuncSetAttribute(moe_gemm, cudaFuncAttributeMaxDynamicSharedMemorySize, SMEM_TOTAL);

    prelude_kernel<<<368, 256>>>(x, map_w, map_b, cent, prior, pw_w, bias_w);
    moe_gemm<<<148, 256, SMEM_TOTAL>>>(x, bias_b, out, out_size);
}

// round 11
// speedup vs baseline: 4.9523x; 1.5395x over previous
#include <cuda_runtime.h>
#include <cuda_fp16.h>
#include <cstdint>

// ---------------------------------------------------------------------------
// Problem constants
// ---------------------------------------------------------------------------
constexpr int N_TOK = 16384;   // T*B
constexpr int C     = 512;
constexpr int O     = 512;
constexpr int RD    = 64;
constexpr int NE    = 8;
constexpr int NSL   = NE + 1;          // 8 expert slices + bias slice

// tcgen05 path tiling: BM=256 (2x M=128 atoms), BN=256, BK=64
constexpr int BM_TC = 256, BN_TC = 256, BK_TC = 64;
constexpr int NKT_TC = NSL * C / BK_TC;                    // 72
constexpr unsigned NTILES_TC = (N_TOK / BM_TC) * (O / BN_TC);  // 128

// legacy path tiling (portable PTX pass only)
constexpr int BM_LG = 128, BN_LG = 256, BK_LG = 32;
constexpr int NKT_LG = NSL * (C / BK_LG);                  // 144
constexpr unsigned NTILES_LG = (N_TOK / BM_LG) * (O / BN_LG);  // 256

// Scratch (static device globals — no allocation)
__device__ float g_resp[N_TOK * NE];
__device__ float g_psum[N_TOK / 64];                 // 256 per-block denom sums
__device__ __align__(16) __half g_wh[NSL * O * C];   // fp16 weights: experts 0..7, then bias_w
__device__ unsigned g_tile_ctr;

// ---------------------------------------------------------------------------
// Arch-specific gate: tcgen05 only exists in the sm_103a cubin pass.
// ---------------------------------------------------------------------------
#if defined(__CUDA_ARCH_FEAT_SM103_ALL) || defined(__CUDA_ARCH_FEAT_SM100_ALL) || \
    defined(__CUDA_ARCH_SPECIFIC__) || defined(__CUDA_ARCH_FAMILY_SPECIFIC__)
#define USE_TC 1
#endif

// ---------------------------------------------------------------------------
// Common helpers
// ---------------------------------------------------------------------------
__device__ __forceinline__ uint32_t smem_u32(const void* p) {
    uint32_t a;
    asm("{ .reg .u64 t; cvta.to.shared.u64 t, %1; cvt.u32.u64 %0, t; }" : "=r"(a) : "l"(p));
    return a;
}
__device__ __forceinline__ void cpa16(uint32_t dst, const void* src) {
    asm volatile("cp.async.cg.shared.global [%0], [%1], 16;" :: "r"(dst), "l"(src));
}
#define CP_COMMIT() asm volatile("cp.async.commit_group;" ::: "memory")
#define CP_WAIT0()  asm volatile("cp.async.wait_group 0;" ::: "memory")

__device__ __forceinline__ uint32_t pack_h2(float lo, float hi) {
    __half2 h = __floats2half2_rn(lo, hi);
    return *reinterpret_cast<uint32_t*>(&h);
}
__device__ __forceinline__ uint32_t swz(uint32_t off) {   // SW128: Swizzle<3,4,3>
    return off ^ ((off >> 3) & 0x70);
}

// ---- legacy mma.sync helpers ----
__device__ __forceinline__ void mma_f16(float (&c)[4], const uint32_t (&a)[4], const uint32_t (&b)[2]) {
    asm volatile(
        "mma.sync.aligned.m16n8k16.row.col.f32.f16.f16.f32 "
        "{%0,%1,%2,%3}, {%4,%5,%6,%7}, {%8,%9}, {%0,%1,%2,%3};\n"
        : "+f"(c[0]), "+f"(c[1]), "+f"(c[2]), "+f"(c[3])
        : "r"(a[0]), "r"(a[1]), "r"(a[2]), "r"(a[3]), "r"(b[0]), "r"(b[1]));
}
__device__ __forceinline__ void ldsm_x4(uint32_t& r0, uint32_t& r1, uint32_t& r2, uint32_t& r3,
                                        uint32_t addr) {
    asm volatile("ldmatrix.sync.aligned.m8n8.x4.shared.b16 {%0,%1,%2,%3}, [%4];"
        : "=r"(r0), "=r"(r1), "=r"(r2), "=r"(r3) : "r"(addr));
}

// ---- tcgen05 helpers (arch-specific pass only) ----
#ifdef USE_TC
#define FENCE_ASYNC() asm volatile("fence.proxy.async.shared::cta;" ::: "memory")
__device__ __forceinline__ void mbar_init(uint32_t a, uint32_t cnt) {
    asm volatile("mbarrier.init.shared.b64 [%0], %1;" :: "r"(a), "r"(cnt) : "memory");
}
__device__ __forceinline__ void mbar_wait(uint32_t a, uint32_t parity) {
    asm volatile(
        "{\n\t.reg .pred P;\n\t"
        "W_%=:\n\t"
        "mbarrier.try_wait.parity.shared::cta.b64 P, [%0], %1, 0x989680;\n\t"
        "@P bra.uni D_%=;\n\t"
        "bra.uni W_%=;\n\t"
        "D_%=:\n\t}"
        :: "r"(a), "r"(parity) : "memory");
}
__device__ __forceinline__ uint32_t elect1() {
    uint32_t p;
    asm volatile("{ .reg .pred q; elect.sync _|q, 0xFFFFFFFF; selp.b32 %0, 1, 0, q; }" : "=r"(p));
    return p;
}
__device__ __forceinline__ void tcommit(uint32_t bar) {
    asm volatile(
        "tcgen05.commit.cta_group::1.mbarrier::arrive::one.shared::cluster.b64 [%0];"
        :: "r"(bar) : "memory");
}
__device__ __forceinline__ void mma_f16_ss(uint32_t d, uint64_t da, uint64_t db,
                                           uint32_t idesc, uint32_t en) {
    asm volatile(
        "{\n\t.reg .pred p;\n\t"
        "setp.ne.u32 p, %4, 0;\n\t"
        "tcgen05.mma.cta_group::1.kind::f16 [%0], %1, %2, %3, {%5, %5, %5, %5}, p;\n\t"
        "}"
        :: "r"(d), "l"(da), "l"(db), "r"(idesc), "r"(en), "r"(0u) : "memory");
}
#define TM_ALLOC(sm, n)   asm volatile("tcgen05.alloc.cta_group::1.sync.aligned.shared::cta.b32 [%0], %1;" :: "r"(sm), "r"((uint32_t)(n)) : "memory")
#define TM_RELINQ()       asm volatile("tcgen05.relinquish_alloc_permit.cta_group::1.sync.aligned;")
#define TM_DEALLOC(t, n)  asm volatile("tcgen05.dealloc.cta_group::1.sync.aligned.b32 %0, %1;" :: "r"(t), "r"((uint32_t)(n)))
#define TM_FENCE_AFTER()  asm volatile("tcgen05.fence::after_thread_sync;" ::: "memory")
#define TM_WAIT_LD()      asm volatile("tcgen05.wait::ld.sync.aligned;" ::: "memory")
#define TM_LD_X32(r, addr) \
    asm volatile( \
        "tcgen05.ld.sync.aligned.32x32b.x32.b32 " \
        "{%0, %1, %2, %3, %4, %5, %6, %7, " \
        " %8, %9, %10, %11, %12, %13, %14, %15, " \
        " %16, %17, %18, %19, %20, %21, %22, %23, " \
        " %24, %25, %26, %27, %28, %29, %30, %31}, [%32];" \
        : "=r"((r)[0]),  "=r"((r)[1]),  "=r"((r)[2]),  "=r"((r)[3]), \
          "=r"((r)[4]),  "=r"((r)[5]),  "=r"((r)[6]),  "=r"((r)[7]), \
          "=r"((r)[8]),  "=r"((r)[9]),  "=r"((r)[10]), "=r"((r)[11]), \
          "=r"((r)[12]), "=r"((r)[13]), "=r"((r)[14]), "=r"((r)[15]), \
          "=r"((r)[16]), "=r"((r)[17]), "=r"((r)[18]), "=r"((r)[19]), \
          "=r"((r)[20]), "=r"((r)[21]), "=r"((r)[22]), "=r"((r)[23]), \
          "=r"((r)[24]), "=r"((r)[25]), "=r"((r)[26]), "=r"((r)[27]), \
          "=r"((r)[28]), "=r"((r)[29]), "=r"((r)[30]), "=r"((r)[31]) \
        : "r"(addr))

// SMEM desc: SW128, version=1, SBO=64, LBO=1 (K-major 128B rows)
constexpr uint64_t DESC_BASE =
    (uint64_t(2) << 61) | (uint64_t(1) << 46) | (uint64_t(64) << 32) | (uint64_t(1) << 16);
__device__ __forceinline__ uint64_t make_desc(uint32_t addr) {
    return DESC_BASE | ((uint64_t)(addr >> 4) & 0x3FFF);
}
// idesc kind::f16: dtype=F32 (1<<4), atype=btype=F16 (0), N=256 -> 32<<17, M=128 -> 8<<24
constexpr uint32_t IDESC_F16 = (1u << 4) | (32u << 17) | (8u << 24);
#endif  // USE_TC

// ---------------------------------------------------------------------------
// SMEM layout (shared by both paths; tcgen05 sizing governs)
// ---------------------------------------------------------------------------
constexpr uint32_t OFF_RESP = 0;        // 256*8*4 = 8192
constexpr uint32_t OFF_BIAS = 8192;     // 256*4   = 1024
constexpr uint32_t OFF_TM   = 9216;     // 8
constexpr uint32_t OFF_BARS = 9224;     // 16
constexpr uint32_t TC_A0 = 10240;       // 256*128B = 32 KB (1024-aligned)
constexpr uint32_t TC_A1 = 43008;
constexpr uint32_t TC_B0 = 75776;
constexpr uint32_t TC_B1 = 108544;      // ends 141312
// legacy 80B-pitch tiles reuse the same regions
constexpr uint32_t LG_A0 = TC_A0, LG_A1 = TC_A1, LG_B0 = TC_B0, LG_B1 = TC_B1;
constexpr uint32_t SMEM_TOTAL = 141312 + 1024;

// ---------------------------------------------------------------------------
// Phase 1 (fused): blocks [0,256) = GMM responsibilities (64 tokens each);
//                  blocks [256,368) = weight fp16 conversion; ctr reset.
// ---------------------------------------------------------------------------
__global__ __launch_bounds__(256) void prelude_kernel(
    const float* __restrict__ x, const float* __restrict__ map_w,
    const float* __restrict__ map_b, const float* __restrict__ cent,
    const float* __restrict__ prior,
    const float* __restrict__ pw, const float* __restrict__ bw)
{
    const int tid = threadIdx.x;

    if (blockIdx.x >= 256) {      // ---- weight conversion ----
        if (blockIdx.x == 256 && tid == 0) g_tile_ctr = 0;
        const int nTot = NSL * O * C / 4;
        const int nPw  = NE  * O * C / 4;
        const int stride = 112 * 256;
        for (int f = (blockIdx.x - 256) * 256 + tid; f < nTot; f += stride) {
            float4 v = (f < nPw) ? ((const float4*)pw)[f] : ((const float4*)bw)[f - nPw];
            uint2 h;
            h.x = pack_h2(v.x, v.y);
            h.y = pack_h2(v.z, v.w);
            ((uint2*)g_wh)[f] = h;
        }
        return;
    }

    // ---- responsibilities ----
    __shared__ float xs[16][68];
    __shared__ float ws[16][68];
    __shared__ float s_k[64][65];
    __shared__ float s_cent[NE][RD];
    __shared__ float s_cc[NE], s_lp[NE], s_mb[RD];
    __shared__ float s_d[64];

    const int t0 = blockIdx.x * 64;

    for (int i = tid; i < NE * RD; i += 256) s_cent[i / RD][i % RD] = cent[i];
    if (tid < NE) {
        float cc = 0.f;
        #pragma unroll
        for (int j = 0; j < RD; ++j) { float c = cent[tid * RD + j]; cc = fmaf(c, c, cc); }
        s_cc[tid] = cc;
        s_lp[tid] = logf(prior[tid]);
    }
    if (tid < RD) s_mb[tid] = map_b[tid];

    const int ty = tid >> 4, tx = tid & 15;
    const int lr = tid >> 2, lq = tid & 3;

    float acc[4][4];
    #pragma unroll
    for (int i = 0; i < 4; ++i)
        #pragma unroll
        for (int j = 0; j < 4; ++j) acc[i][j] = 0.f;

    for (int ct = 0; ct < C / 16; ++ct) {
        const float4 xv = *(const float4*)(x     + (size_t)(t0 + lr) * C + ct * 16 + lq * 4);
        const float4 wv = *(const float4*)(map_w + (size_t)lr        * C + ct * 16 + lq * 4);
        __syncthreads();
        xs[lq * 4 + 0][lr] = xv.x; xs[lq * 4 + 1][lr] = xv.y;
        xs[lq * 4 + 2][lr] = xv.z; xs[lq * 4 + 3][lr] = xv.w;
        ws[lq * 4 + 0][lr] = wv.x; ws[lq * 4 + 1][lr] = wv.y;
        ws[lq * 4 + 2][lr] = wv.z; ws[lq * 4 + 3][lr] = wv.w;
        __syncthreads();
        #pragma unroll
        for (int kk = 0; kk < 16; ++kk) {
            const float4 a = *(const float4*)&xs[kk][ty * 4];
            const float4 b = *(const float4*)&ws[kk][tx * 4];
            const float av[4] = {a.x, a.y, a.z, a.w};
            const float bv[4] = {b.x, b.y, b.z, b.w};
            #pragma unroll
            for (int i = 0; i < 4; ++i)
                #pragma unroll
                for (int j = 0; j < 4; ++j) acc[i][j] = fmaf(av[i], bv[j], acc[i][j]);
        }
    }
    __syncthreads();
    #pragma unroll
    for (int i = 0; i < 4; ++i)
        #pragma unroll
        for (int j = 0; j < 4; ++j)
            s_k[ty * 4 + i][tx * 4 + j] = acc[i][j] + s_mb[tx * 4 + j];
    __syncthreads();

    if (tid < 64) {
        float kk = 0.f, kc[NE];
        #pragma unroll
        for (int e = 0; e < NE; ++e) kc[e] = 0.f;
        #pragma unroll 8
        for (int j = 0; j < RD; ++j) {
            const float kj = s_k[tid][j];
            kk = fmaf(kj, kj, kk);
            #pragma unroll
            for (int e = 0; e < NE; ++e) kc[e] = fmaf(kj, s_cent[e][j], kc[e]);
        }
        const float LOG2PI = 1.8378770664093453f;
        float lr8[NE], m = -1e30f;
        #pragma unroll
        for (int e = 0; e < NE; ++e) {
            lr8[e] = -0.5f * (kk + s_cc[e] - 2.f * kc[e]) - (RD * 0.5f) * LOG2PI + s_lp[e];
            m = fmaxf(m, lr8[e]);
        }
        float s = 0.f;
        #pragma unroll
        for (int e = 0; e < NE; ++e) s += expf(lr8[e] - m);
        const float denom = m + logf(s);
        float4 r0, r1;
        r0.x = expf(lr8[0] - denom); r0.y = expf(lr8[1] - denom);
        r0.z = expf(lr8[2] - denom); r0.w = expf(lr8[3] - denom);
        r1.x = expf(lr8[4] - denom); r1.y = expf(lr8[5] - denom);
        r1.z = expf(lr8[6] - denom); r1.w = expf(lr8[7] - denom);
        const int tok = t0 + tid;
        *(float4*)&g_resp[tok * NE + 0] = r0;
        *(float4*)&g_resp[tok * NE + 4] = r1;
        s_d[tid] = denom;
    }
    __syncthreads();
    if (tid < 8) {
        float a = 0.f;
        #pragma unroll
        for (int j = 0; j < 8; ++j) a += s_d[tid * 8 + j];
        s_d[tid] = a;
    }
    __syncthreads();
    if (tid == 0) {
        float a = 0.f;
        #pragma unroll
        for (int j = 0; j < 8; ++j) a += s_d[j];
        g_psum[blockIdx.x] = a;
    }
}

// ---------------------------------------------------------------------------
// Phase 2: GEMM + fused loss.  y = A_big @ B_big^T + bias_b
//   tcgen05: one 256x256 tile per CTA (grid 129, CTA 128 = loss), MMA-first
//   software pipeline. Legacy fallback: persistent R8 loop.
// ---------------------------------------------------------------------------
__global__ __launch_bounds__(256, 1) void moe_gemm(
    const float* __restrict__ x, const float* __restrict__ bias_b,
    float* __restrict__ out, int out_size)
{
    extern __shared__ __align__(128) char smem_raw[];
    const uint32_t sb_raw = smem_u32(smem_raw);
    const uint32_t pad = (1024u - (sb_raw & 1023u)) & 1023u;
    char* smem = smem_raw + pad;
    const uint32_t sb = sb_raw + pad;

    const int tid = threadIdx.x;
    const int warp = tid >> 5, lane = tid & 31;

    float* respS = (float*)(smem + OFF_RESP);
    float* biasS = (float*)(smem + OFF_BIAS);
    __shared__ float s_red[256];

#ifdef USE_TC
    // =================== tcgen05 path: 1 tile per CTA ===================
    if (blockIdx.x >= NTILES_TC) {      // ---- loss CTA ----
        s_red[tid] = g_psum[tid];
        __syncthreads();
        for (int w = 128; w > 0; w >>= 1) {
            if (tid < w) s_red[tid] += s_red[tid + w];
            __syncthreads();
        }
        if (tid == 0) {
            const float loss = -0.1f * s_red[0];
            for (long i = (long)N_TOK * O; i < out_size; ++i) out[i] = loss;
        }
        return;
    }

    const int bm = blockIdx.x >> 1, bn = blockIdx.x & 1;

    if (warp == 0) { TM_ALLOC(sb + OFF_TM, 512); TM_RELINQ(); }
    if (tid == 0) { mbar_init(sb + OFF_BARS, 1); mbar_init(sb + OFF_BARS + 8, 1); }

    // preload resp tile (8KB) + bias_b slice
    ((float4*)respS)[tid]       = ((const float4*)(g_resp + (size_t)bm * BM_TC * NE))[tid];
    ((float4*)respS)[tid + 256] = ((const float4*)(g_resp + (size_t)bm * BM_TC * NE))[tid + 256];
    if (tid < 64) ((float4*)biasS)[tid] = ((const float4*)(bias_b + bn * BN_TC))[tid];

    float4 xv[16];                      // 64 x-floats: row tid of current i0 chunk
    auto ldgX = [&](int i0c) {
        const float4* p = (const float4*)(x + (size_t)(bm * BM_TC + tid) * C + i0c);
        #pragma unroll
        for (int q = 0; q < 16; ++q) xv[q] = p[q];
    };
    auto stsA = [&](int e, uint32_t offA) {
        const float s = (e < NE) ? respS[tid * NE + e] : 1.0f;
        #pragma unroll
        for (int q = 0; q < 8; ++q) {
            uint4 h;
            h.x = pack_h2(xv[q * 2].x * s,     xv[q * 2].y * s);
            h.y = pack_h2(xv[q * 2].z * s,     xv[q * 2].w * s);
            h.z = pack_h2(xv[q * 2 + 1].x * s, xv[q * 2 + 1].y * s);
            h.w = pack_h2(xv[q * 2 + 1].z * s, xv[q * 2 + 1].w * s);
            *(uint4*)(smem + offA + swz(tid * 128 + q * 16)) = h;
        }
    };
    auto issueB = [&](int e, int i0c, uint32_t offB) {
        const __half* base = g_wh + ((size_t)e * O + bn * BN_TC) * C + i0c;
        #pragma unroll
        for (int it = 0; it < 8; ++it) {
            const int f = tid + it * 256;
            const int row = f >> 3, q = f & 7;
            cpa16(sb + offB + swz(row * 128 + q * 16), base + (size_t)row * C + q * 8);
        }
    };

    __syncthreads();                    // TM_ALLOC + mbar_init done
    uint32_t tmem;
    asm volatile("ld.shared.b32 %0, [%1];" : "=r"(tmem) : "r"(sb + OFF_TM));

    // prologue: stage 0
    ldgX(0);
    issueB(0, 0, TC_B0);
    CP_COMMIT();
    __syncthreads();                    // resp/bias visible
    stsA(0, TC_A0);
    CP_WAIT0();
    FENCE_ASYNC();
    __syncthreads();                    // buffer 0 fully ready

    const uint64_t dA[2] = { make_desc(sb + TC_A0), make_desc(sb + TC_A1) };
    const uint64_t dB[2] = { make_desc(sb + TC_B0), make_desc(sb + TC_B1) };

    for (int kt = 0; kt < NKT_TC; ++kt) {
        const int s = kt & 1;

        // ---- MMA first: operands for kt are resident in buffer s ----
        if (warp == 0 && elect1()) {
            #pragma unroll
            for (int k = 0; k < 4; ++k) {
                const uint32_t en = (kt | k) ? 1u : 0u;
                mma_f16_ss(tmem,       dA[s] + k * 2,        dB[s] + k * 2, IDESC_F16, en);
                mma_f16_ss(tmem + 256, dA[s] + 1024 + k * 2, dB[s] + k * 2, IDESC_F16, en);
            }
            tcommit(sb + OFF_BARS + 8 * s);
        }

        // ---- load kt+1 into buffer s^1 underneath the MMA ----
        if (kt + 1 < NKT_TC) {
            if (kt >= 1) mbar_wait(sb + OFF_BARS + 8 * (s ^ 1), ((kt - 1) >> 1) & 1);
            const int e1 = (kt + 1) % NSL;
            const int i1 = ((kt + 1) / NSL) * BK_TC;
            issueB(e1, i1, s ? TC_B0 : TC_B1);
            CP_COMMIT();
            if (e1 == 0) ldgX(i1);
            stsA(e1, s ? TC_A0 : TC_A1);
            CP_WAIT0();
            FENCE_ASYNC();
        }
        __syncthreads();
    }

    // wait for the last commit (bar1; 36th commit -> parity 1)
    mbar_wait(sb + OFF_BARS + 8 * ((NKT_TC - 1) & 1), ((NKT_TC - 1) >> 1) & 1);
    TM_FENCE_AFTER();

    // epilogue: all 8 warps; warps 0-3 -> M-atom0 (cols 0..255),
    //           warps 4-7 -> M-atom1 (cols 256..511, rows +128)
    {
        const int atom = warp >> 2, wsub = warp & 3;
        const int row = bm * BM_TC + atom * 128 + wsub * 32 + lane;
        const uint32_t tbase = tmem + atom * 256;
        float* dst = out + (size_t)row * O + bn * BN_TC;
        #pragma unroll 1
        for (int c = 0; c < 8; ++c) {
            uint32_t r[32];
            TM_LD_X32(r, tbase + c * 32);
            TM_WAIT_LD();
            #pragma unroll
            for (int q = 0; q < 8; ++q) {
                const float4 bb = *(const float4*)&biasS[c * 32 + q * 4];
                float4 v;
                v.x = __uint_as_float(r[q * 4 + 0]) + bb.x;
                v.y = __uint_as_float(r[q * 4 + 1]) + bb.y;
                v.z = __uint_as_float(r[q * 4 + 2]) + bb.z;
                v.w = __uint_as_float(r[q * 4 + 3]) + bb.w;
                *(float4*)(dst + c * 32 + q * 4) = v;
            }
        }
    }
    __syncthreads();
    if (warp == 0) TM_DEALLOC(tmem, 512);

#else
    // =================== legacy mma.sync fallback (R8-proven) ===================
    __shared__ unsigned s_tile;
    const int wm = warp >> 2, wn = warp & 3;
    const int g = lane >> 2, tg = lane & 3;
    const int arow = tid >> 1;
    const int aseg = tid & 1;

    const uint32_t aOff = (uint32_t)(wm * 64 + (lane & 15)) * 80 + (uint32_t)(lane >> 4) * 16;
    const uint32_t bOff = (uint32_t)(wn * 64 + (lane & 7)) * 80 + (uint32_t)(lane >> 3) * 16;

    for (;;) {
        __syncthreads();
        if (tid == 0) s_tile = atomicAdd(&g_tile_ctr, 1u);
        __syncthreads();
        const unsigned t = s_tile;
        if (t > NTILES_LG) break;
        if (t == NTILES_LG) {
            s_red[tid] = g_psum[tid];
            __syncthreads();
            for (int w = 128; w > 0; w >>= 1) {
                if (tid < w) s_red[tid] += s_red[tid + w];
                __syncthreads();
            }
            if (tid == 0) {
                const float loss = -0.1f * s_red[0];
                for (long i = (long)N_TOK * O; i < out_size; ++i) out[i] = loss;
            }
            continue;
        }
        const int bm = t >> 1, bn = t & 1;

        ((float4*)respS)[tid] = ((const float4*)(g_resp + (size_t)bm * BM_LG * NE))[tid];
        if (tid < 64) ((float4*)biasS)[tid] = ((const float4*)(bias_b + bn * BN_LG))[tid];

        float4 xv[4];
        auto ldgX = [&](int i0c) {
            const float4* p = (const float4*)(x + (size_t)(bm * BM_LG + arow) * C + i0c + aseg * 16);
            xv[0] = p[0]; xv[1] = p[1]; xv[2] = p[2]; xv[3] = p[3];
        };
        auto stsA = [&](int e, uint32_t offA) {
            const float s = (e < NE) ? respS[arow * NE + e] : 1.0f;
            uint4 h0, h1;
            h0.x = pack_h2(xv[0].x * s, xv[0].y * s);
            h0.y = pack_h2(xv[0].z * s, xv[0].w * s);
            h0.z = pack_h2(xv[1].x * s, xv[1].y * s);
            h0.w = pack_h2(xv[1].z * s, xv[1].w * s);
            h1.x = pack_h2(xv[2].x * s, xv[2].y * s);
            h1.y = pack_h2(xv[2].z * s, xv[2].w * s);
            h1.z = pack_h2(xv[3].x * s, xv[3].y * s);
            h1.w = pack_h2(xv[3].z * s, xv[3].w * s);
            uint4* dst = (uint4*)(smem + offA + arow * 80 + aseg * 32);
            dst[0] = h0; dst[1] = h1;
        };
        auto issueB = [&](int e, int i0c, uint32_t offB) {
            const __half* base = g_wh + ((size_t)e * O + bn * BN_LG) * C + i0c;
            #pragma unroll
            for (int k = 0; k < 4; ++k) {
                const int c = tid + k * 256;
                const int row = c >> 2, q = c & 3;
                cpa16(sb + offB + row * 80 + q * 16, base + (size_t)row * C + q * 8);
            }
        };

        float acc[4][8][4];
        #pragma unroll
        for (int a = 0; a < 4; ++a)
            #pragma unroll
            for (int b = 0; b < 8; ++b)
                #pragma unroll
                for (int c = 0; c < 4; ++c) acc[a][b][c] = 0.f;

        ldgX(0);
        issueB(0, 0, LG_B0);
        CP_COMMIT();
        __syncthreads();
        stsA(0, LG_A0);
        CP_WAIT0();
        __syncthreads();

        for (int kt = 0; kt < NKT_LG; ++kt) {
            const int s = kt & 1;
            const bool more = (kt + 1 < NKT_LG);
            int e1 = 0;
            if (more) {
                e1 = (kt + 1) % NSL;
                const int i1 = ((kt + 1) / NSL) * BK_LG;
                issueB(e1, i1, s ? LG_B0 : LG_B1);
                CP_COMMIT();
                if (e1 == 0) ldgX(i1);
            }
            {
                const uint32_t A0 = sb + (s ? LG_A1 : LG_A0);
                const uint32_t B0 = sb + (s ? LG_B1 : LG_B0);
                uint32_t af[2][4][4], bf[2][8][2];
                #pragma unroll
                for (int mt = 0; mt < 4; ++mt) {
                    ldsm_x4(af[0][mt][0], af[0][mt][1], af[0][mt][2], af[0][mt][3],
                            A0 + aOff + mt * 1280);
                    ldsm_x4(af[1][mt][0], af[1][mt][1], af[1][mt][2], af[1][mt][3],
                            A0 + aOff + mt * 1280 + 32);
                }
                #pragma unroll
                for (int nt = 0; nt < 8; ++nt) {
                    uint32_t r0, r1, r2, r3;
                    ldsm_x4(r0, r1, r2, r3, B0 + bOff + nt * 640);
                    bf[0][nt][0] = r0; bf[0][nt][1] = r1;
                    bf[1][nt][0] = r2; bf[1][nt][1] = r3;
                }
                #pragma unroll
                for (int ks = 0; ks < 2; ++ks)
                    #pragma unroll
                    for (int mt = 0; mt < 4; ++mt)
                        #pragma unroll
                        for (int nt = 0; nt < 8; ++nt)
                            mma_f16(acc[mt][nt], af[ks][mt], bf[ks][nt]);
            }
            if (more) {
                stsA(e1, s ? LG_A0 : LG_A1);
                CP_WAIT0();
            }
            __syncthreads();
        }

        #pragma unroll
        for (int mt = 0; mt < 4; ++mt) {
            const int row = bm * BM_LG + wm * 64 + mt * 16 + g;
            #pragma unroll
            for (int nt = 0; nt < 8; ++nt) {
                const int cb = wn * 64 + nt * 8 + tg * 2;
                const float b0 = biasS[cb], b1 = biasS[cb + 1];
                float2 v0 = make_float2(acc[mt][nt][0] + b0, acc[mt][nt][1] + b1);
                float2 v1 = make_float2(acc[mt][nt][2] + b0, acc[mt][nt][3] + b1);
                float* dst = out + (size_t)row * O + bn * BN_LG + cb;
                *(float2*)dst = v0;
                *(float2*)(dst + 8 * O) = v1;
            }
        }
    }
#endif
}

// ---------------------------------------------------------------------------
extern "C" void kernel_launch(void* const* d_in, const int* in_sizes, int n_in,
                              void* d_out, int out_size)
{
    const float* x      = (const float*)d_in[0];
    // d_in[1] = key_feat, ignored by the forward pass
    const float* map_w  = (const float*)d_in[2];
    const float* map_b  = (const float*)d_in[3];
    const float* cent   = (const float*)d_in[4];
    const float* prior  = (const float*)d_in[5];
    const float* pw_w   = (const float*)d_in[6];
    const float* bias_w = (const float*)d_in[7];
    const float* bias_b = (const float*)d_in[8];
    float* out = (float*)d_out;

    cudaFuncSetAttribute(moe_gemm, cudaFuncAttributeMaxDynamicSharedMemorySize, SMEM_TOTAL);

    prelude_kernel<<<368, 256>>>(x, map_w, map_b, cent, prior, pw_w, bias_w);
    moe_gemm<<<NTILES_TC + 1, 256, SMEM_TOTAL>>>(x, bias_b, out, out_size);
}